// round 14
// baseline (speedup 1.0000x reference)
#include <cuda_runtime.h>
#include <cuda_bf16.h>
#include <math.h>
#include <stdint.h>

#define BB 8
#define LL 2048
#define DD 512
#define HH 8
#define DH 64
#define DFF 2048
#define UU 40
#define NCAND 128
#define NSPLIT 4
#define NS 2
#define NBH (BB*HH)

// ---------------- scratch (no allocs allowed) ----------------
__device__ float g_k[NBH*LL*DH];
__device__ float g_v[NBH*LL*DH];
__device__ __nv_bfloat16 g_xh[BB*LL*DD];    // bf16 input
__device__ __nv_bfloat16 g_wqt[DD*DD];      // Wq^T bf16  [n][e]
__device__ __nv_bfloat16 g_wkt[DD*DD];      // Wk^T bf16  [n][e]
__device__ __nv_bfloat16 g_qh[NBH*LL*DH];   // bf16 q (approx)
__device__ __nv_bfloat16 g_kh[NBH*LL*DH];   // bf16 k (approx)
__device__ float g_M[NBH*LL];
__device__ float g_xsp[8*BB*DD];            // x row-sum partials
__device__ float g_ksum[NBH*DH];
__device__ float g_vmean[NBH*DH];
__device__ int   g_cand[NBH*NCAND];
__device__ float g_qc[NBH*NCAND*DH];        // exact fp32 q for candidates
__device__ float g_rmaxp[NSPLIT*NBH*NCAND];
__device__ float g_dotc[NBH*NCAND];
__device__ int   g_topslot[NBH*UU];
__device__ float g_pm[NS*NBH*UU];
__device__ float g_pl[NS*NBH*UU];
__device__ float g_pO[NS*NBH*UU*DH];

__device__ __forceinline__ uint32_t smem_u32(const void* p) {
    uint32_t a;
    asm("{ .reg .u64 t; cvta.to.shared.u64 t, %1; cvt.u32.u64 %0, t; }"
        : "=r"(a) : "l"(p));
    return a;
}
#define SWZ(b) ((b) ^ (((b) >> 3) & 0x70))

__device__ __forceinline__ uint32_t f2ord(float f) {
    uint32_t u = __float_as_uint(f);
    return (u & 0x80000000u) ? ~u : (u | 0x80000000u);
}

// ============ Kernel 0: x -> bf16, Wq^T & Wk^T -> bf16 ============
#define CVT_XBLKS 4096
__global__ __launch_bounds__(256) void cvt_kernel(
    const float* __restrict__ x, const float* __restrict__ Wq,
    const float* __restrict__ Wk)
{
    const int bidx = blockIdx.x, tid = threadIdx.x;
    if (bidx < CVT_XBLKS) {
        size_t base = (size_t)bidx*2048 + tid*8;
        float4 a = *(const float4*)&x[base];
        float4 b = *(const float4*)&x[base+4];
        *(__nv_bfloat162*)&g_xh[base]   = __nv_bfloat162(__float2bfloat16_rn(a.x), __float2bfloat16_rn(a.y));
        *(__nv_bfloat162*)&g_xh[base+2] = __nv_bfloat162(__float2bfloat16_rn(a.z), __float2bfloat16_rn(a.w));
        *(__nv_bfloat162*)&g_xh[base+4] = __nv_bfloat162(__float2bfloat16_rn(b.x), __float2bfloat16_rn(b.y));
        *(__nv_bfloat162*)&g_xh[base+6] = __nv_bfloat162(__float2bfloat16_rn(b.z), __float2bfloat16_rn(b.w));
    } else if (bidx < CVT_XBLKS + 128) {
        int i = bidx - CVT_XBLKS;            // 0..127
        int n = i*4 + (tid >> 6);
        int e0 = tid & 63;
        #pragma unroll
        for (int j = 0; j < 8; j++) {
            int e = e0 + 64*j;
            g_wqt[n*512 + e] = __float2bfloat16_rn(Wq[(size_t)e*512 + n]);
        }
    } else {
        int i = bidx - (CVT_XBLKS + 128);    // 0..127
        int n = i*4 + (tid >> 6);
        int e0 = tid & 63;
        #pragma unroll
        for (int j = 0; j < 8; j++) {
            int e = e0 + 64*j;
            g_wkt[n*512 + e] = __float2bfloat16_rn(Wk[(size_t)e*512 + n]);
        }
    }
}

// ============ Kernel 1: x row-sum partials (for ksum/vmean trick) ==========
__global__ __launch_bounds__(256) void xsum_kernel(const float* __restrict__ x)
{
    const int b = blockIdx.x, ch = blockIdx.y, tid = threadIdx.x;
    const float* xp = x + ((size_t)b*LL + ch*256)*512;
    float s0 = 0.f, s1 = 0.f;
    for (int l = 0; l < 256; l++) {
        s0 += xp[(size_t)l*512 + tid];
        s1 += xp[(size_t)l*512 + tid + 256];
    }
    g_xsp[((size_t)ch*BB + b)*512 + tid]       = s0;
    g_xsp[((size_t)ch*BB + b)*512 + tid + 256] = s1;
}

// ===== Kernel 2: ksum = xsum@Wk + L*bk ; vmean = (xsum@Wv)/L + bv ==========
__global__ __launch_bounds__(256) void ksumv_kernel(
    const float* __restrict__ Wk, const float* __restrict__ bk,
    const float* __restrict__ Wv, const float* __restrict__ bv)
{
    const int b = blockIdx.x, tid = threadIdx.x;
    __shared__ float xs[512];
    for (int i = tid; i < 512; i += 256) {
        float s = 0.f;
        #pragma unroll
        for (int ch = 0; ch < 8; ch++)
            s += g_xsp[((size_t)ch*BB + b)*512 + i];
        xs[i] = s;
    }
    __syncthreads();
    #pragma unroll
    for (int rep = 0; rep < 2; rep++) {
        int n = tid + rep*256;
        float ka = 0.f, va = 0.f;
        #pragma unroll 4
        for (int e = 0; e < 512; e++) {
            float xv = xs[e];
            ka = fmaf(xv, Wk[(size_t)e*512 + n], ka);
            va = fmaf(xv, Wv[(size_t)e*512 + n], va);
        }
        int h = n >> 6, d = n & 63;
        g_ksum[(b*HH + h)*64 + d]  = ka + (float)LL * bk[n];
        g_vmean[(b*HH + h)*64 + d] = va * (1.0f/LL) + bv[n];
    }
}

// ================= Kernel 3: K/V projection (fp32, stream B) ===============
__global__ __launch_bounds__(256) void kv_kernel(
    const float* __restrict__ x,
    const float* __restrict__ Wk, const float* __restrict__ bk,
    const float* __restrict__ Wv, const float* __restrict__ bv)
{
    const int z = blockIdx.z;
    const float* __restrict__ W    = (z==0) ? Wk : Wv;
    const float* __restrict__ bias = (z==0) ? bk : bv;
    float* __restrict__ outp       = (z==0) ? g_k : g_v;

    __shared__ float Xs[16][132];
    __shared__ float Ws[16][68];

    const int m0 = blockIdx.x * 128;
    const int n0 = blockIdx.y * 64;
    const int tid = threadIdx.x;
    const int tn = tid & 15;
    const int tm = tid >> 4;

    float acc[8][4];
    #pragma unroll
    for (int i = 0; i < 8; i++)
        #pragma unroll
        for (int j = 0; j < 4; j++) acc[i][j] = 0.f;

    for (int k0 = 0; k0 < 512; k0 += 16) {
        #pragma unroll
        for (int it = 0; it < 2; it++) {
            int idx = tid + it*256;
            int r = idx >> 2, c = idx & 3;
            float4 xv = *(const float4*)&x[(size_t)(m0 + r)*512 + k0 + c*4];
            Xs[c*4+0][r] = xv.x; Xs[c*4+1][r] = xv.y;
            Xs[c*4+2][r] = xv.z; Xs[c*4+3][r] = xv.w;
        }
        {
            int r = tid >> 4, c = tid & 15;
            float4 wv = *(const float4*)&W[(size_t)(k0 + r)*512 + n0 + c*4];
            *(float4*)&Ws[r][c*4] = wv;
        }
        __syncthreads();
        #pragma unroll
        for (int kk = 0; kk < 16; kk++) {
            float4 a0 = *(float4*)&Xs[kk][tm*8];
            float4 a1 = *(float4*)&Xs[kk][tm*8+4];
            float4 b0 = *(float4*)&Ws[kk][tn*4];
            float am[8] = {a0.x,a0.y,a0.z,a0.w,a1.x,a1.y,a1.z,a1.w};
            float bn[4] = {b0.x,b0.y,b0.z,b0.w};
            #pragma unroll
            for (int i = 0; i < 8; i++)
                #pragma unroll
                for (int j = 0; j < 4; j++)
                    acc[i][j] = fmaf(am[i], bn[j], acc[i][j]);
        }
        __syncthreads();
    }

    const int h = n0 >> 6;
    float4 b4 = *(const float4*)&bias[n0 + tn*4];
    #pragma unroll
    for (int i = 0; i < 8; i++) {
        int r  = m0 + tm*8 + i;
        int bb = r >> 11, l = r & 2047;
        size_t base = ((size_t)(bb*HH + h)*LL + l)*64 + tn*4;
        *(float4*)&outp[base] = make_float4(acc[i][0]+b4.x, acc[i][1]+b4.y,
                                            acc[i][2]+b4.z, acc[i][3]+b4.w);
    }
}

// ---------------- mma helpers ----------------
__device__ __forceinline__ void ldmA(uint32_t* a, uint32_t addr) {
    asm volatile("ldmatrix.sync.aligned.m8n8.x4.shared.b16 {%0,%1,%2,%3}, [%4];"
        : "=r"(a[0]),"=r"(a[1]),"=r"(a[2]),"=r"(a[3]) : "r"(addr));
}
__device__ __forceinline__ void ldmB4(uint32_t* b, uint32_t addr) {
    asm volatile("ldmatrix.sync.aligned.m8n8.x4.shared.b16 {%0,%1,%2,%3}, [%4];"
        : "=r"(b[0]),"=r"(b[1]),"=r"(b[2]),"=r"(b[3]) : "r"(addr));
}
__device__ __forceinline__ void mma16816(float* c, const uint32_t* a, const uint32_t* b) {
    asm volatile(
        "mma.sync.aligned.m16n8k16.row.col.f32.bf16.bf16.f32 "
        "{%0,%1,%2,%3}, {%4,%5,%6,%7}, {%8,%9}, {%0,%1,%2,%3};"
        : "+f"(c[0]),"+f"(c[1]),"+f"(c[2]),"+f"(c[3])
        : "r"(a[0]),"r"(a[1]),"r"(a[2]),"r"(a[3]), "r"(b[0]),"r"(b[1]));
}

// ===== Kernel 4: Q/K projection in bf16 HMMA (z=0 -> Q, z=1 -> K) ==========
#define QP_A 0
#define QP_B 8192
__global__ __launch_bounds__(256) void proj_kernel(
    const float* __restrict__ bq, const float* __restrict__ bk)
{
    __shared__ char smem[24576];
    const uint32_t sb = smem_u32(smem);
    const int z = blockIdx.z;
    const __nv_bfloat16* __restrict__ wt = (z==0) ? g_wqt : g_wkt;
    const float* __restrict__ bias       = (z==0) ? bq    : bk;
    __nv_bfloat16* __restrict__ outp     = (z==0) ? g_qh  : g_kh;

    const int tid = threadIdx.x, wid = tid >> 5, lane = tid & 31;
    const int m0 = blockIdx.x * 64, n0 = blockIdx.y * 128;

    const int qg = wid >> 1, kg = wid & 1;
    const int ag = lane >> 3, ar = lane & 7;
    const int arow  = qg*16 + ((ag & 1) << 3) + ar;
    const int ahalf = (ag >> 1) << 3;
    const int bm = lane >> 3, brw = lane & 7;
    const int b_nboff = bm >> 1, b_half = (bm & 1) << 3;

    float acc[8][4];
    #pragma unroll
    for (int nb = 0; nb < 8; nb++)
        #pragma unroll
        for (int j = 0; j < 4; j++) acc[nb][j] = 0.f;

    for (int kc0 = 0; kc0 < 8; kc0++) {
        __syncthreads();
        #pragma unroll
        for (int it = 0; it < 2; it++) {
            int i = tid + it*256;
            int row = i >> 3, c = i & 7;
            const char* ap = (const char*)(g_xh + (size_t)(m0+row)*512 + kc0*64);
            *(uint4*)(smem + QP_A + SWZ(row*128 + c*16)) = *(const uint4*)(ap + c*16);
        }
        #pragma unroll
        for (int it = 0; it < 4; it++) {
            int i = tid + it*256;
            int row = i >> 3, c = i & 7;
            const char* bp = (const char*)(wt + (size_t)(n0+row)*512 + kc0*64);
            *(uint4*)(smem + QP_B + SWZ(row*128 + c*16)) = *(const uint4*)(bp + c*16);
        }
        __syncthreads();

        #pragma unroll
        for (int kc = 0; kc < 4; kc++) {
            uint32_t Ah[4];
            ldmA(Ah, sb + QP_A + SWZ(arow*128 + (kc*16 + ahalf)*2));
            #pragma unroll
            for (int nbp = 0; nbp < 8; nbp += 2) {
                uint32_t Bh[4];
                int nrow = kg*64 + (nbp + b_nboff)*8 + brw;
                ldmB4(Bh, sb + QP_B + SWZ(nrow*128 + (kc*16 + b_half)*2));
                mma16816(acc[nbp],   Ah, Bh);
                mma16816(acc[nbp+1], Ah, Bh+2);
            }
        }
    }

    const int r_lo = m0 + qg*16 + (lane >> 2);
    const int colb = (lane & 3) * 2;
    #pragma unroll
    for (int nb = 0; nb < 8; nb++) {
        int n = n0 + kg*64 + nb*8 + colb;
        int h = n >> 6, d = n & 63;
        float2 b2 = *(const float2*)&bias[n];
        #pragma unroll
        for (int rr = 0; rr < 2; rr++) {
            int m = r_lo + rr*8;
            int bb = m >> 11, l = m & 2047;
            float v0 = acc[nb][rr*2+0] + b2.x;
            float v1 = acc[nb][rr*2+1] + b2.y;
            *(__nv_bfloat162*)&outp[((size_t)(bb*HH + h)*LL + l)*64 + d] =
                __nv_bfloat162(__float2bfloat16_rn(v0), __float2bfloat16_rn(v1));
        }
    }
}

// ======= Kernel 5: approx QK^T row-max via single-term bf16 mma.sync =======
#define M2_QH 0
#define M2_KH 8192
#define M2_KS 24576
#define M2_MB 24832
#define M2_SMEM (M2_MB + 2*64*4)

__global__ __launch_bounds__(256) void maxpass1_kernel()
{
    extern __shared__ char smem[];
    const uint32_t sb = smem_u32(smem);
    const int tid = threadIdx.x, wid = tid >> 5, lane = tid & 31;
    const int bh = blockIdx.y, q0 = blockIdx.x * 64;

    if (tid < 64) *(float*)(smem + M2_KS + tid*4) = g_ksum[bh*64 + tid];

    {   // Q tile: 64 rows x 128B, SW128
        const char* qh = (const char*)(g_qh + ((size_t)bh*LL + q0)*64);
        #pragma unroll
        for (int it = 0; it < 2; it++) {
            int byte = (tid + it*256) * 16;
            *(uint4*)(smem + M2_QH + SWZ(byte)) = *(const uint4*)(qh + byte);
        }
    }

    const int qg = wid >> 1, kg = wid & 1;
    const int ag = lane >> 3, ar = lane & 7;
    const int arow  = qg*16 + ((ag & 1) << 3) + ar;
    const int ahalf = (ag >> 1) << 3;
    const int bm = lane >> 3, brw = lane & 7;
    const int b_nboff = bm >> 1, b_half = (bm & 1) << 3;

    float rmax0 = -INFINITY, rmax1 = -INFINITY;

    for (int kt = 0; kt < LL/128; kt++) {
        __syncthreads();
        {
            const char* kh = (const char*)(g_kh + ((size_t)bh*LL + kt*128)*64);
            #pragma unroll
            for (int it = 0; it < 4; it++) {
                int byte = (tid + it*256) * 16;
                *(uint4*)(smem + M2_KH + SWZ(byte)) = *(const uint4*)(kh + byte);
            }
        }
        __syncthreads();

        float acc[8][4];
        #pragma unroll
        for (int nb = 0; nb < 8; nb++)
            #pragma unroll
            for (int j = 0; j < 4; j++) acc[nb][j] = 0.f;

        #pragma unroll
        for (int kc = 0; kc < 4; kc++) {
            uint32_t Ah[4];
            ldmA(Ah, sb + M2_QH + SWZ(arow*128 + (kc*16 + ahalf)*2));
            #pragma unroll
            for (int nbp = 0; nbp < 8; nbp += 2) {
                uint32_t Bh[4];
                int key = kg*64 + (nbp + b_nboff)*8 + brw;
                ldmB4(Bh, sb + M2_KH + SWZ(key*128 + (kc*16 + b_half)*2));
                mma16816(acc[nbp],   Ah, Bh);
                mma16816(acc[nbp+1], Ah, Bh+2);
            }
        }
        #pragma unroll
        for (int nb = 0; nb < 8; nb++) {
            rmax0 = fmaxf(rmax0, fmaxf(acc[nb][0], acc[nb][1]));
            rmax1 = fmaxf(rmax1, fmaxf(acc[nb][2], acc[nb][3]));
        }
    }

    rmax0 = fmaxf(rmax0, __shfl_xor_sync(0xffffffffu, rmax0, 1));
    rmax0 = fmaxf(rmax0, __shfl_xor_sync(0xffffffffu, rmax0, 2));
    rmax1 = fmaxf(rmax1, __shfl_xor_sync(0xffffffffu, rmax1, 1));
    rmax1 = fmaxf(rmax1, __shfl_xor_sync(0xffffffffu, rmax1, 2));
    float* mb = (float*)(smem + M2_MB);
    const int r0 = qg*16 + (lane >> 2);
    if ((lane & 3) == 0) {
        mb[kg*64 + r0]     = rmax0;
        mb[kg*64 + r0 + 8] = rmax1;
    }
    __syncthreads();
    if (tid < 64) {
        float m = fmaxf(mb[tid], mb[64 + tid]);
        float dot = 0.f;
        #pragma unroll
        for (int d = 0; d < 64; d++) {
            float qv = __bfloat162float(*(__nv_bfloat16*)(smem + M2_QH + SWZ(tid*128 + d*2)));
            dot = fmaf(qv, *(float*)(smem + M2_KS + d*4), dot);
        }
        g_M[(size_t)bh*LL + q0 + tid] = m - dot * (1.0f/LL);
    }
}

// ========== Kernel 6: top-128 candidates per (b,h) via bitonic sort =========
__global__ __launch_bounds__(256) void topcand_kernel()
{
    const int bh = blockIdx.x, tid = threadIdx.x;
    __shared__ unsigned long long arr[LL];
    for (int i = tid; i < LL; i += 256) {
        uint32_t key = f2ord(g_M[(size_t)bh*LL + i]);
        arr[i] = ((unsigned long long)key << 32) | (uint32_t)i;
    }
    __syncthreads();
    for (int k = 2; k <= LL; k <<= 1) {
        for (int j = k >> 1; j > 0; j >>= 1) {
            for (int i = tid; i < LL; i += 256) {
                int l = i ^ j;
                if (l > i) {
                    unsigned long long a = arr[i], b = arr[l];
                    bool up = ((i & k) == 0);
                    if (up ? (a < b) : (a > b)) { arr[i] = b; arr[l] = a; }
                }
            }
            __syncthreads();
        }
    }
    if (tid < NCAND)
        g_cand[bh*NCAND + tid] = (int)(arr[tid] & 0xFFFFFFFFu);
}

// ===== Kernel 7: exact fp32 Q for candidates: g_qc[bh][c][64] =====
__global__ __launch_bounds__(256) void qcand_kernel(
    const float* __restrict__ x, const float* __restrict__ Wq,
    const float* __restrict__ bq)
{
    const int bh = blockIdx.y, half = blockIdx.x;
    const int b = bh >> 3, h = bh & 7;
    const int tid = threadIdx.x;
    const int d4 = tid & 15, ec = tid >> 4;
    __shared__ float xr[512];
    __shared__ float4 p4[256];

    for (int c = 0; c < 64; c++) {
        int cand = half*64 + c;
        int l = g_cand[bh*NCAND + cand];
        __syncthreads();
        *(float2*)&xr[tid*2] = *(const float2*)&x[((size_t)b*LL + l)*512 + tid*2];
        __syncthreads();

        float4 acc = make_float4(0.f,0.f,0.f,0.f);
        #pragma unroll 8
        for (int e = ec*32; e < ec*32 + 32; e++) {
            float xv = xr[e];
            float4 w = *(const float4*)&Wq[(size_t)e*512 + h*64 + d4*4];
            acc.x = fmaf(xv, w.x, acc.x); acc.y = fmaf(xv, w.y, acc.y);
            acc.z = fmaf(xv, w.z, acc.z); acc.w = fmaf(xv, w.w, acc.w);
        }
        p4[tid] = acc;
        __syncthreads();
        for (int s = 8; s > 0; s >>= 1) {
            if (ec < s) {
                float4 o = p4[tid + s*16];
                acc.x += o.x; acc.y += o.y; acc.z += o.z; acc.w += o.w;
                p4[tid] = acc;
            }
            __syncthreads();
        }
        if (ec == 0) {
            float4 bqv = *(const float4*)&bq[h*64 + d4*4];
            *(float4*)&g_qc[((size_t)bh*NCAND + cand)*64 + d4*4] =
                make_float4(acc.x+bqv.x, acc.y+bqv.y, acc.z+bqv.z, acc.w+bqv.w);
        }
    }
}

// ========== Kernel 8: exact fp32 rescore — tiled GEMM over key splits =======
__global__ __launch_bounds__(256,2) void rescore2_kernel()
{
    extern __shared__ float dsm[];
    float* Qs = dsm;
    float* Ks = dsm + 64*128;
    float* ks = dsm + 2*64*128;

    const int bh = blockIdx.y;
    const int sp = blockIdx.x;
    const int tid = threadIdx.x;
    const int tx  = tid & 15;
    const int ty  = tid >> 4;

    if (tid < 64) ks[tid] = g_ksum[bh*64 + tid];

    #pragma unroll
    for (int it = 0; it < 8; it++) {
        int idx = tid + it*256;
        int cc = idx & 127, d4 = idx >> 7;
        float4 v = *(const float4*)&g_qc[((size_t)bh*NCAND + cc)*64 + d4*4];
        Qs[(4*d4+0)*128 + cc] = v.x; Qs[(4*d4+1)*128 + cc] = v.y;
        Qs[(4*d4+2)*128 + cc] = v.z; Qs[(4*d4+3)*128 + cc] = v.w;
    }

    float rmax[8];
    #pragma unroll
    for (int i = 0; i < 8; i++) rmax[i] = -INFINITY;

    const int kt0 = sp * (LL/128/NSPLIT);
    for (int kt = kt0; kt < kt0 + LL/128/NSPLIT; kt++) {
        __syncthreads();
        #pragma unroll
        for (int it = 0; it < 8; it++) {
            int idx = tid + it*256;
            int ss = idx & 127, d4 = idx >> 7;
            float4 v = *(const float4*)&g_k[((size_t)bh*LL + kt*128 + ss)*64 + d4*4];
            Ks[(4*d4+0)*128 + ss] = v.x; Ks[(4*d4+1)*128 + ss] = v.y;
            Ks[(4*d4+2)*128 + ss] = v.z; Ks[(4*d4+3)*128 + ss] = v.w;
        }
        __syncthreads();

        float acc[8][8];
        #pragma unroll
        for (int i = 0; i < 8; i++)
            #pragma unroll
            for (int j = 0; j < 8; j++) acc[i][j] = 0.f;

        #pragma unroll 4
        for (int kk = 0; kk < 64; kk++) {
            float4 qa = *(float4*)&Qs[kk*128 + ty*8];
            float4 qb = *(float4*)&Qs[kk*128 + ty*8 + 4];
            float4 ka = *(float4*)&Ks[kk*128 + tx*8];
            float4 kb = *(float4*)&Ks[kk*128 + tx*8 + 4];
            float am[8] = {qa.x,qa.y,qa.z,qa.w,qb.x,qb.y,qb.z,qb.w};
            float bm[8] = {ka.x,ka.y,ka.z,ka.w,kb.x,kb.y,kb.z,kb.w};
            #pragma unroll
            for (int i = 0; i < 8; i++)
                #pragma unroll
                for (int j = 0; j < 8; j++)
                    acc[i][j] = fmaf(am[i], bm[j], acc[i][j]);
        }
        #pragma unroll
        for (int i = 0; i < 8; i++) {
            float m = acc[i][0];
            #pragma unroll
            for (int j = 1; j < 8; j++) m = fmaxf(m, acc[i][j]);
            rmax[i] = fmaxf(rmax[i], m);
        }
    }

    float dotv[8];
    #pragma unroll
    for (int i = 0; i < 8; i++) dotv[i] = 0.f;
    if (sp == 0) {
        #pragma unroll
        for (int c = 0; c < 4; c++) {
            float kv = ks[tx*4 + c];
            #pragma unroll
            for (int i = 0; i < 8; i++)
                dotv[i] = fmaf(Qs[(tx*4+c)*128 + ty*8 + i], kv, dotv[i]);
        }
    }
    #pragma unroll
    for (int i = 0; i < 8; i++) {
        float m = rmax[i], dsum = dotv[i];
        #pragma unroll
        for (int off = 8; off > 0; off >>= 1) {
            m    = fmaxf(m, __shfl_xor_sync(0xffffffffu, m, off, 16));
            dsum +=          __shfl_xor_sync(0xffffffffu, dsum, off, 16);
        }
        if (tx == 0) {
            int cc = ty*8 + i;
            g_rmaxp[((size_t)sp*NBH + bh)*NCAND + cc] = m;
            if (sp == 0) g_dotc[bh*NCAND + cc] = dsum;
        }
    }
}

// ========== Kernel 9: combine splits + exact top-40 (slots) ================
__global__ __launch_bounds__(128) void select40_kernel()
{
    const int bh = blockIdx.x, tid = threadIdx.x;
    __shared__ unsigned long long arr[NCAND];
    {
        float m = -INFINITY;
        #pragma unroll
        for (int sp = 0; sp < NSPLIT; sp++)
            m = fmaxf(m, g_rmaxp[((size_t)sp*NBH + bh)*NCAND + tid]);
        float Mex = m - g_dotc[bh*NCAND + tid] * (1.0f/LL);
        arr[tid] = ((unsigned long long)f2ord(Mex) << 32) | (uint32_t)tid;
    }
    __syncthreads();
    for (int k = 2; k <= NCAND; k <<= 1) {
        for (int j = k >> 1; j > 0; j >>= 1) {
            int l = tid ^ j;
            if (l > tid) {
                unsigned long long a = arr[tid], b = arr[l];
                bool up = ((tid & k) == 0);
                if (up ? (a < b) : (a > b)) { arr[tid] = b; arr[l] = a; }
            }
            __syncthreads();
        }
    }
    if (tid < UU)
        g_topslot[bh*UU + tid] = (int)(arr[tid] & 0xFFFFFFFFu);
}

// ===== Kernel 10: flash-style attention, all 40 queries per (bh,split) ======
#define TA_QS 0
#define TA_KT 10240
#define TA_VT (TA_KT + 32768)
#define TA_SC (TA_VT + 32768)
#define TA_IDX (TA_SC + 20480)
#define TA_SMEM (TA_IDX + 256)

__global__ __launch_bounds__(256) void topattn2_kernel()
{
    extern __shared__ char smem[];
    float* qs = (float*)(smem + TA_QS);
    float* Kt = (float*)(smem + TA_KT);
    float* Vt = (float*)(smem + TA_VT);
    float* sc = (float*)(smem + TA_SC);
    int*   idx = (int*)(smem + TA_IDX);

    const int sp = blockIdx.x, bh = blockIdx.y;
    const int tid = threadIdx.x, w = tid >> 5, lane = tid & 31;

    if (tid < UU) idx[tid] = g_topslot[bh*UU + tid];
    __syncthreads();
    for (int i = tid; i < UU*16; i += 256) {
        int r = i >> 4, c = i & 15;
        float4 v = *(const float4*)&g_qc[((size_t)bh*NCAND + idx[r])*64 + c*4];
        qs[r*64 + c*4+0] = v.x*0.125f; qs[r*64 + c*4+1] = v.y*0.125f;
        qs[r*64 + c*4+2] = v.z*0.125f; qs[r*64 + c*4+3] = v.w*0.125f;
    }

    float m[5], l[5], O[5][2];
    #pragma unroll
    for (int qi = 0; qi < 5; qi++) {
        m[qi] = -INFINITY; l[qi] = 0.f; O[qi][0] = 0.f; O[qi][1] = 0.f;
    }

    const int kt0 = sp * (LL/128/NS);
    for (int kt = kt0; kt < kt0 + LL/128/NS; kt++) {
        __syncthreads();
        #pragma unroll
        for (int it = 0; it < 8; it++) {
            int i = tid + it*256;
            int ss = i & 127, d4 = i >> 7;
            float4 v = *(const float4*)&g_k[((size_t)bh*LL + kt*128 + ss)*64 + d4*4];
            Kt[(4*d4+0)*128 + ss] = v.x; Kt[(4*d4+1)*128 + ss] = v.y;
            Kt[(4*d4+2)*128 + ss] = v.z; Kt[(4*d4+3)*128 + ss] = v.w;
        }
        #pragma unroll
        for (int it = 0; it < 8; it++) {
            int i = tid + it*256;
            int ss = i >> 4, c = i & 15;
            *(float4*)&Vt[ss*64 + c*4] =
                *(const float4*)&g_v[((size_t)bh*LL + kt*128 + ss)*64 + c*4];
        }
        __syncthreads();

        float s4[5][4];
        #pragma unroll
        for (int qi = 0; qi < 5; qi++)
            #pragma unroll
            for (int j = 0; j < 4; j++) s4[qi][j] = 0.f;

        #pragma unroll 4
        for (int d = 0; d < 64; d++) {
            float4 kv = *(float4*)&Kt[d*128 + lane*4];
            #pragma unroll
            for (int qi = 0; qi < 5; qi++) {
                float qv = qs[(w*5 + qi)*64 + d];
                s4[qi][0] = fmaf(qv, kv.x, s4[qi][0]);
                s4[qi][1] = fmaf(qv, kv.y, s4[qi][1]);
                s4[qi][2] = fmaf(qv, kv.z, s4[qi][2]);
                s4[qi][3] = fmaf(qv, kv.w, s4[qi][3]);
            }
        }

        float scale[5];
        #pragma unroll
        for (int qi = 0; qi < 5; qi++) {
            float tm = fmaxf(fmaxf(s4[qi][0], s4[qi][1]), fmaxf(s4[qi][2], s4[qi][3]));
            #pragma unroll
            for (int off = 16; off > 0; off >>= 1)
                tm = fmaxf(tm, __shfl_xor_sync(0xffffffffu, tm, off));
            float mn = fmaxf(m[qi], tm);
            scale[qi] = expf(m[qi] - mn);
            float4 p;
            p.x = expf(s4[qi][0] - mn); p.y = expf(s4[qi][1] - mn);
            p.z = expf(s4[qi][2] - mn); p.w = expf(s4[qi][3] - mn);
            *(float4*)&sc[(w*5 + qi)*128 + lane*4] = p;
            float ls = p.x + p.y + p.z + p.w;
            #pragma unroll
            for (int off = 16; off > 0; off >>= 1)
                ls += __shfl_xor_sync(0xffffffffu, ls, off);
            l[qi] = l[qi]*scale[qi] + ls;
            m[qi] = mn;
        }
        __syncwarp();

        #pragma unroll
        for (int qi = 0; qi < 5; qi++) { O[qi][0] *= scale[qi]; O[qi][1] *= scale[qi]; }

        #pragma unroll 4
        for (int s = 0; s < 128; s++) {
            float2 vv = *(float2*)&Vt[s*64 + lane*2];
            #pragma unroll
            for (int qi = 0; qi < 5; qi++) {
                float p = sc[(w*5 + qi)*128 + s];
                O[qi][0] = fmaf(p, vv.x, O[qi][0]);
                O[qi][1] = fmaf(p, vv.y, O[qi][1]);
            }
        }
        __syncwarp();
    }

    #pragma unroll
    for (int qi = 0; qi < 5; qi++) {
        int r = w*5 + qi;
        size_t base = ((size_t)(sp*NBH + bh)*UU + r);
        *(float2*)&g_pO[base*64 + lane*2] = make_float2(O[qi][0], O[qi][1]);
        if (lane == 0) { g_pm[base] = m[qi]; g_pl[base] = l[qi]; }
    }
}

// ================= Kernel 11: decoder tail (per-batch) =================
__global__ __launch_bounds__(256) void final_kernel(
    const float* __restrict__ Wo, const float* __restrict__ bo,
    const float* __restrict__ W1, const float* __restrict__ b1,
    const float* __restrict__ W2, const float* __restrict__ b2,
    const float* __restrict__ ga1, const float* __restrict__ be1,
    const float* __restrict__ ga2, const float* __restrict__ be2,
    const float* __restrict__ Wout, const float* __restrict__ bout,
    float* __restrict__ d_out)
{
    const int b = blockIdx.x, tid = threadIdx.x;
    __shared__ float ctxm[512], av[512], yv[512], ffv[2048], ov[512], red[256];
    __shared__ float wA[HH*UU], wB[HH*UU];
    __shared__ float s_m, s_inv;

    for (int i = tid; i < HH*UU; i += 256) {
        int h = i / UU, r = i % UU;
        size_t b0 = (size_t)(0*NBH + b*HH + h)*UU + r;
        size_t b1i = (size_t)(1*NBH + b*HH + h)*UU + r;
        float m1 = g_pm[b0], m2 = g_pm[b1i];
        float l1 = g_pl[b0], l2 = g_pl[b1i];
        float mm = fmaxf(m1, m2);
        float w1 = expf(m1 - mm), w2 = expf(m2 - mm);
        float den = w1*l1 + w2*l2;
        wA[i] = w1/den; wB[i] = w2/den;
    }
    __syncthreads();

    #pragma unroll
    for (int k = 0; k < 2; k++) {
        int d = tid + k*256;
        int h = d >> 6, dd = d & 63;
        int bh = b*HH + h;
        float val = g_vmean[bh*64 + dd] * (float)(LL - UU);
        for (int r = 0; r < UU; r++) {
            float o1 = g_pO[((size_t)(0*NBH + bh)*UU + r)*64 + dd];
            float o2 = g_pO[((size_t)(1*NBH + bh)*UU + r)*64 + dd];
            val += wA[h*UU + r]*o1 + wB[h*UU + r]*o2;
        }
        ctxm[d] = val * (1.0f/LL);
    }
    __syncthreads();

    #pragma unroll
    for (int k = 0; k < 2; k++) {
        int d = tid + k*256;
        float acc = 0.f;
        for (int e = 0; e < 512; e++)
            acc = fmaf(ctxm[e], Wo[(size_t)e*512 + d], acc);
        av[d] = acc + bo[d];
    }
    __syncthreads();

    red[tid] = 2.f*av[tid] + 2.f*av[tid+256];
    __syncthreads();
    for (int s = 128; s > 0; s >>= 1) { if (tid < s) red[tid] += red[tid+s]; __syncthreads(); }
    if (tid == 0) s_m = red[0] * (1.0f/512.f);
    __syncthreads();
    {
        float t0 = 2.f*av[tid] - s_m, t1 = 2.f*av[tid+256] - s_m;
        red[tid] = t0*t0 + t1*t1;
        __syncthreads();
        for (int s = 128; s > 0; s >>= 1) { if (tid < s) red[tid] += red[tid+s]; __syncthreads(); }
        if (tid == 0) s_inv = 1.0f / sqrtf(red[0]*(1.0f/512.f) + 1e-5f);
        __syncthreads();
        yv[tid]     = t0 * s_inv * ga1[tid]     + be1[tid];
        yv[tid+256] = t1 * s_inv * ga1[tid+256] + be1[tid+256];
    }
    __syncthreads();

    #pragma unroll
    for (int it = 0; it < 8; it++) {
        int f = tid + it*256;
        const float4* wp = (const float4*)&W1[(size_t)f*512];
        float acc = 0.f;
        #pragma unroll 8
        for (int c = 0; c < 128; c++) {
            float4 ww = wp[c];
            acc = fmaf(ww.x, yv[4*c+0], acc);
            acc = fmaf(ww.y, yv[4*c+1], acc);
            acc = fmaf(ww.z, yv[4*c+2], acc);
            acc = fmaf(ww.w, yv[4*c+3], acc);
        }
        ffv[f] = fmaxf(acc + b1[f], 0.f);
    }
    __syncthreads();

    #pragma unroll
    for (int k = 0; k < 2; k++) {
        int d = tid + k*256;
        const float4* wp = (const float4*)&W2[(size_t)d*2048];
        float acc = 0.f;
        #pragma unroll 8
        for (int c = 0; c < 512; c++) {
            float4 ww = wp[c];
            acc = fmaf(ww.x, ffv[4*c+0], acc);
            acc = fmaf(ww.y, ffv[4*c+1], acc);
            acc = fmaf(ww.z, ffv[4*c+2], acc);
            acc = fmaf(ww.w, ffv[4*c+3], acc);
        }
        ov[d] = yv[d] + acc + b2[d];
    }
    __syncthreads();

    red[tid] = ov[tid] + ov[tid+256];
    __syncthreads();
    for (int s = 128; s > 0; s >>= 1) { if (tid < s) red[tid] += red[tid+s]; __syncthreads(); }
    if (tid == 0) s_m = red[0] * (1.0f/512.f);
    __syncthreads();
    {
        float t0 = ov[tid] - s_m, t1 = ov[tid+256] - s_m;
        red[tid] = t0*t0 + t1*t1;
        __syncthreads();
        for (int s = 128; s > 0; s >>= 1) { if (tid < s) red[tid] += red[tid+s]; __syncthreads(); }
        if (tid == 0) s_inv = 1.0f / sqrtf(red[0]*(1.0f/512.f) + 1e-5f);
        __syncthreads();
        float o0 = t0 * s_inv * ga2[tid]     + be2[tid];
        float o1 = t1 * s_inv * ga2[tid+256] + be2[tid+256];
        ov[tid] = o0; ov[tid+256] = o1;
        d_out[BB + (size_t)b*512 + tid]       = o0;
        d_out[BB + (size_t)b*512 + tid + 256] = o1;
    }
    __syncthreads();

    red[tid] = ov[tid]*Wout[tid] + ov[tid+256]*Wout[tid+256];
    __syncthreads();
    for (int s = 128; s > 0; s >>= 1) { if (tid < s) red[tid] += red[tid+s]; __syncthreads(); }
    if (tid == 0) d_out[b] = red[0] + bout[0];
}

// ================= host launcher =================
extern "C" void kernel_launch(void* const* d_in, const int* in_sizes, int n_in,
                              void* d_out, int out_size)
{
    const float* x    = (const float*)d_in[0];
    const float* Wq   = (const float*)d_in[1];
    const float* bq   = (const float*)d_in[2];
    const float* Wk   = (const float*)d_in[3];
    const float* bk   = (const float*)d_in[4];
    const float* Wv   = (const float*)d_in[5];
    const float* bv   = (const float*)d_in[6];
    const float* Wo   = (const float*)d_in[7];
    const float* bo   = (const float*)d_in[8];
    const float* W1   = (const float*)d_in[9];
    const float* b1   = (const float*)d_in[10];
    const float* W2   = (const float*)d_in[11];
    const float* b2   = (const float*)d_in[12];
    const float* ga1  = (const float*)d_in[13];
    const float* be1  = (const float*)d_in[14];
    const float* ga2  = (const float*)d_in[15];
    const float* be2  = (const float*)d_in[16];
    const float* Wout = (const float*)d_in[17];
    const float* bout = (const float*)d_in[18];
    float* out = (float*)d_out;

    static cudaStream_t sB = nullptr;
    static cudaEvent_t evF = nullptr, evJ = nullptr;
    if (sB == nullptr) {
        cudaStreamCreateWithFlags(&sB, cudaStreamNonBlocking);
        cudaEventCreateWithFlags(&evF, cudaEventDisableTiming);
        cudaEventCreateWithFlags(&evJ, cudaEventDisableTiming);
        const int rs_smem = (2*64*128 + 64) * (int)sizeof(float);
        cudaFuncSetAttribute(maxpass1_kernel,
                             cudaFuncAttributeMaxDynamicSharedMemorySize, M2_SMEM);
        cudaFuncSetAttribute(rescore2_kernel,
                             cudaFuncAttributeMaxDynamicSharedMemorySize, rs_smem);
        cudaFuncSetAttribute(topattn2_kernel,
                             cudaFuncAttributeMaxDynamicSharedMemorySize, TA_SMEM);
    }
    const int rs_smem = (2*64*128 + 64) * (int)sizeof(float);

    // ---- fork: fp32 K/V GEMM on stream B (FMA pipe) ----
    cudaEventRecord(evF, 0);
    cudaStreamWaitEvent(sB, evF, 0);
    kv_kernel<<<dim3(128, 8, 2), 256, 0, sB>>>(x, Wk, bk, Wv, bv);
    cudaEventRecord(evJ, sB);

    // ---- stream A: screening chain (tensor/LDSM pipes) ----
    cvt_kernel<<<CVT_XBLKS + 256, 256>>>(x, Wq, Wk);
    xsum_kernel<<<dim3(BB, 8), 256>>>(x);
    ksumv_kernel<<<BB, 256>>>(Wk, bk, Wv, bv);
    proj_kernel<<<dim3(256, 4, 2), 256>>>(bq, bk);
    maxpass1_kernel<<<dim3(LL/64, NBH), 256, M2_SMEM>>>();
    topcand_kernel<<<NBH, 256>>>();
    qcand_kernel<<<dim3(2, NBH), 256>>>(x, Wq, bq);

    // ---- join: exact path needs fp32 K/V ----
    cudaStreamWaitEvent(0, evJ, 0);
    rescore2_kernel<<<dim3(NSPLIT, NBH), 256, rs_smem>>>();
    select40_kernel<<<NBH, 128>>>();
    topattn2_kernel<<<dim3(NS, NBH), 256, TA_SMEM>>>();
    final_kernel<<<BB, 256>>>(Wo, bo, W1, b1, W2, b2,
                              ga1, be1, ga2, be2, Wout, bout, out);
}

// round 15
// speedup vs baseline: 1.1088x; 1.1088x over previous
#include <cuda_runtime.h>
#include <cuda_bf16.h>
#include <math.h>
#include <stdint.h>

#define BB 8
#define LL 2048
#define DD 512
#define HH 8
#define DH 64
#define DFF 2048
#define UU 40
#define NCAND 128
#define NSPLIT 4
#define NS 2
#define NBH (BB*HH)

// ---------------- scratch (no allocs allowed) ----------------
__device__ float g_k[NBH*LL*DH];
__device__ float g_v[NBH*LL*DH];
__device__ __nv_bfloat16 g_xh[BB*LL*DD];    // bf16 input
__device__ __nv_bfloat16 g_wqt[DD*DD];      // Wq^T bf16  [n][e]
__device__ __nv_bfloat16 g_qh[NBH*LL*DH];   // bf16 q (approx)
__device__ __nv_bfloat16 g_kh[NBH*LL*DH];   // bf16 k
__device__ float g_M[NBH*LL];
__device__ float g_ksp[4*NBH*DH];           // stats partials
__device__ float g_vsp[4*NBH*DH];
__device__ float g_ksum[NBH*DH];
__device__ float g_vmean[NBH*DH];
__device__ int   g_cand[NBH*NCAND];
__device__ float g_qc[NBH*NCAND*DH];        // exact fp32 q for candidates
__device__ float g_rmaxp[NSPLIT*NBH*NCAND];
__device__ float g_dotc[NBH*NCAND];
__device__ int   g_topslot[NBH*UU];
__device__ float g_pm[NS*NBH*UU];
__device__ float g_pl[NS*NBH*UU];
__device__ float g_pO[NS*NBH*UU*DH];

__device__ __forceinline__ uint32_t smem_u32(const void* p) {
    uint32_t a;
    asm("{ .reg .u64 t; cvta.to.shared.u64 t, %1; cvt.u32.u64 %0, t; }"
        : "=r"(a) : "l"(p));
    return a;
}
#define SWZ(b) ((b) ^ (((b) >> 3) & 0x70))

__device__ __forceinline__ uint32_t f2ord(float f) {
    uint32_t u = __float_as_uint(f);
    return (u & 0x80000000u) ? ~u : (u | 0x80000000u);
}

// ============ Kernel 0: x -> bf16, Wq -> bf16 transposed ============
#define CVT_XBLKS 4096
__global__ __launch_bounds__(256) void cvt_kernel(
    const float* __restrict__ x, const float* __restrict__ Wq)
{
    const int bidx = blockIdx.x, tid = threadIdx.x;
    if (bidx < CVT_XBLKS) {
        size_t base = (size_t)bidx*2048 + tid*8;
        float4 a = *(const float4*)&x[base];
        float4 b = *(const float4*)&x[base+4];
        *(__nv_bfloat162*)&g_xh[base]   = __nv_bfloat162(__float2bfloat16_rn(a.x), __float2bfloat16_rn(a.y));
        *(__nv_bfloat162*)&g_xh[base+2] = __nv_bfloat162(__float2bfloat16_rn(a.z), __float2bfloat16_rn(a.w));
        *(__nv_bfloat162*)&g_xh[base+4] = __nv_bfloat162(__float2bfloat16_rn(b.x), __float2bfloat16_rn(b.y));
        *(__nv_bfloat162*)&g_xh[base+6] = __nv_bfloat162(__float2bfloat16_rn(b.z), __float2bfloat16_rn(b.w));
    } else {
        int i = bidx - CVT_XBLKS;            // 0..127
        int n = i*4 + (tid >> 6);
        int e0 = tid & 63;
        #pragma unroll
        for (int j = 0; j < 8; j++) {
            int e = e0 + 64*j;
            g_wqt[n*512 + e] = __float2bfloat16_rn(Wq[(size_t)e*512 + n]);
        }
    }
}

// ================= Kernel 1: K/V projection (fp32) =================
__global__ __launch_bounds__(256) void kv_kernel(
    const float* __restrict__ x,
    const float* __restrict__ Wk, const float* __restrict__ bk,
    const float* __restrict__ Wv, const float* __restrict__ bv)
{
    const int z = blockIdx.z;
    const float* __restrict__ W    = (z==0) ? Wk : Wv;
    const float* __restrict__ bias = (z==0) ? bk : bv;
    float* __restrict__ outp       = (z==0) ? g_k : g_v;

    __shared__ float Xs[16][132];
    __shared__ float Ws[16][68];

    const int m0 = blockIdx.x * 128;
    const int n0 = blockIdx.y * 64;
    const int tid = threadIdx.x;
    const int tn = tid & 15;
    const int tm = tid >> 4;

    float acc[8][4];
    #pragma unroll
    for (int i = 0; i < 8; i++)
        #pragma unroll
        for (int j = 0; j < 4; j++) acc[i][j] = 0.f;

    for (int k0 = 0; k0 < 512; k0 += 16) {
        #pragma unroll
        for (int it = 0; it < 2; it++) {
            int idx = tid + it*256;
            int r = idx >> 2, c = idx & 3;
            float4 xv = *(const float4*)&x[(size_t)(m0 + r)*512 + k0 + c*4];
            Xs[c*4+0][r] = xv.x; Xs[c*4+1][r] = xv.y;
            Xs[c*4+2][r] = xv.z; Xs[c*4+3][r] = xv.w;
        }
        {
            int r = tid >> 4, c = tid & 15;
            float4 wv = *(const float4*)&W[(size_t)(k0 + r)*512 + n0 + c*4];
            *(float4*)&Ws[r][c*4] = wv;
        }
        __syncthreads();
        #pragma unroll
        for (int kk = 0; kk < 16; kk++) {
            float4 a0 = *(float4*)&Xs[kk][tm*8];
            float4 a1 = *(float4*)&Xs[kk][tm*8+4];
            float4 b0 = *(float4*)&Ws[kk][tn*4];
            float am[8] = {a0.x,a0.y,a0.z,a0.w,a1.x,a1.y,a1.z,a1.w};
            float bn[4] = {b0.x,b0.y,b0.z,b0.w};
            #pragma unroll
            for (int i = 0; i < 8; i++)
                #pragma unroll
                for (int j = 0; j < 4; j++)
                    acc[i][j] = fmaf(am[i], bn[j], acc[i][j]);
        }
        __syncthreads();
    }

    const int h = n0 >> 6;
    float4 b4 = *(const float4*)&bias[n0 + tn*4];
    #pragma unroll
    for (int i = 0; i < 8; i++) {
        int r  = m0 + tm*8 + i;
        int bb = r >> 11, l = r & 2047;
        size_t base = ((size_t)(bb*HH + h)*LL + l)*64 + tn*4;
        float o[4] = {acc[i][0]+b4.x, acc[i][1]+b4.y, acc[i][2]+b4.z, acc[i][3]+b4.w};
        *(float4*)&outp[base] = make_float4(o[0],o[1],o[2],o[3]);
        if (z == 0) {
            *(__nv_bfloat162*)&g_kh[base]   =
                __nv_bfloat162(__float2bfloat16_rn(o[0]), __float2bfloat16_rn(o[1]));
            *(__nv_bfloat162*)&g_kh[base+2] =
                __nv_bfloat162(__float2bfloat16_rn(o[2]), __float2bfloat16_rn(o[3]));
        }
    }
}

// ---------------- mma helpers ----------------
__device__ __forceinline__ void ldmA(uint32_t* a, uint32_t addr) {
    asm volatile("ldmatrix.sync.aligned.m8n8.x4.shared.b16 {%0,%1,%2,%3}, [%4];"
        : "=r"(a[0]),"=r"(a[1]),"=r"(a[2]),"=r"(a[3]) : "r"(addr));
}
__device__ __forceinline__ void ldmB4(uint32_t* b, uint32_t addr) {
    asm volatile("ldmatrix.sync.aligned.m8n8.x4.shared.b16 {%0,%1,%2,%3}, [%4];"
        : "=r"(b[0]),"=r"(b[1]),"=r"(b[2]),"=r"(b[3]) : "r"(addr));
}
__device__ __forceinline__ void mma16816(float* c, const uint32_t* a, const uint32_t* b) {
    asm volatile(
        "mma.sync.aligned.m16n8k16.row.col.f32.bf16.bf16.f32 "
        "{%0,%1,%2,%3}, {%4,%5,%6,%7}, {%8,%9}, {%0,%1,%2,%3};"
        : "+f"(c[0]),"+f"(c[1]),"+f"(c[2]),"+f"(c[3])
        : "r"(a[0]),"r"(a[1]),"r"(a[2]),"r"(a[3]), "r"(b[0]),"r"(b[1]));
}

// ===== Kernel 2: Q projection in bf16 HMMA: g_qh = bf16(Xh @ WqT^T + bq) ====
#define QP_A 0
#define QP_B 8192
__global__ __launch_bounds__(256) void qproj_kernel(const float* __restrict__ bq)
{
    __shared__ char smem[24576];
    const uint32_t sb = smem_u32(smem);
    const int tid = threadIdx.x, wid = tid >> 5, lane = tid & 31;
    const int m0 = blockIdx.x * 64, n0 = blockIdx.y * 128;

    const int qg = wid >> 1, kg = wid & 1;
    const int ag = lane >> 3, ar = lane & 7;
    const int arow  = qg*16 + ((ag & 1) << 3) + ar;
    const int ahalf = (ag >> 1) << 3;
    const int bm = lane >> 3, brw = lane & 7;
    const int b_nboff = bm >> 1, b_half = (bm & 1) << 3;

    float acc[8][4];
    #pragma unroll
    for (int nb = 0; nb < 8; nb++)
        #pragma unroll
        for (int j = 0; j < 4; j++) acc[nb][j] = 0.f;

    for (int kc0 = 0; kc0 < 8; kc0++) {
        __syncthreads();
        #pragma unroll
        for (int it = 0; it < 2; it++) {
            int i = tid + it*256;
            int row = i >> 3, c = i & 7;
            const char* ap = (const char*)(g_xh + (size_t)(m0+row)*512 + kc0*64);
            *(uint4*)(smem + QP_A + SWZ(row*128 + c*16)) = *(const uint4*)(ap + c*16);
        }
        #pragma unroll
        for (int it = 0; it < 4; it++) {
            int i = tid + it*256;
            int row = i >> 3, c = i & 7;
            const char* bp = (const char*)(g_wqt + (size_t)(n0+row)*512 + kc0*64);
            *(uint4*)(smem + QP_B + SWZ(row*128 + c*16)) = *(const uint4*)(bp + c*16);
        }
        __syncthreads();

        #pragma unroll
        for (int kc = 0; kc < 4; kc++) {
            uint32_t Ah[4];
            ldmA(Ah, sb + QP_A + SWZ(arow*128 + (kc*16 + ahalf)*2));
            #pragma unroll
            for (int nbp = 0; nbp < 8; nbp += 2) {
                uint32_t Bh[4];
                int nrow = kg*64 + (nbp + b_nboff)*8 + brw;
                ldmB4(Bh, sb + QP_B + SWZ(nrow*128 + (kc*16 + b_half)*2));
                mma16816(acc[nbp],   Ah, Bh);
                mma16816(acc[nbp+1], Ah, Bh+2);
            }
        }
    }

    const int r_lo = m0 + qg*16 + (lane >> 2);
    const int colb = (lane & 3) * 2;
    #pragma unroll
    for (int nb = 0; nb < 8; nb++) {
        int n = n0 + kg*64 + nb*8 + colb;
        int h = n >> 6, d = n & 63;
        float2 bq2 = *(const float2*)&bq[n];
        #pragma unroll
        for (int rr = 0; rr < 2; rr++) {
            int m = r_lo + rr*8;
            int bb = m >> 11, l = m & 2047;
            float v0 = acc[nb][rr*2+0] + bq2.x;
            float v1 = acc[nb][rr*2+1] + bq2.y;
            *(__nv_bfloat162*)&g_qh[((size_t)(bb*HH + h)*LL + l)*64 + d] =
                __nv_bfloat162(__float2bfloat16_rn(v0), __float2bfloat16_rn(v1));
        }
    }
}

// ========== Kernel 3: key-sum & value-mean (4-way split + combine) =========
__global__ __launch_bounds__(256) void stats_kernel()
{
    const int bh = blockIdx.x, p4 = blockIdx.y;
    const int tid = threadIdx.x;
    const int d4 = tid & 15, r = tid >> 4;

    const float4* kp = (const float4*)(g_k + ((size_t)bh*LL + p4*512 + r*32)*64);
    const float4* vp = (const float4*)(g_v + ((size_t)bh*LL + p4*512 + r*32)*64);
    float4 ks = make_float4(0,0,0,0), vs = make_float4(0,0,0,0);
    #pragma unroll 4
    for (int s = 0; s < 32; s++) {
        float4 a = kp[s*16 + d4];
        float4 b = vp[s*16 + d4];
        ks.x += a.x; ks.y += a.y; ks.z += a.z; ks.w += a.w;
        vs.x += b.x; vs.y += b.y; vs.z += b.z; vs.w += b.w;
    }
    __shared__ float4 sk[256], sv[256];
    sk[tid] = ks; sv[tid] = vs;
    __syncthreads();
    for (int s = 8; s > 0; s >>= 1) {
        if (r < s) {
            float4 a = sk[tid + s*16], b = sv[tid + s*16];
            ks.x += a.x; ks.y += a.y; ks.z += a.z; ks.w += a.w;
            vs.x += b.x; vs.y += b.y; vs.z += b.z; vs.w += b.w;
            sk[tid] = ks; sv[tid] = vs;
        }
        __syncthreads();
    }
    if (r == 0) {
        *(float4*)&g_ksp[((size_t)p4*NBH + bh)*64 + d4*4] = ks;
        *(float4*)&g_vsp[((size_t)p4*NBH + bh)*64 + d4*4] = vs;
    }
}

__global__ __launch_bounds__(64) void statcomb_kernel()
{
    const int bh = blockIdx.x, d = threadIdx.x;
    float ks = 0.f, vs = 0.f;
    #pragma unroll
    for (int p = 0; p < 4; p++) {
        ks += g_ksp[((size_t)p*NBH + bh)*64 + d];
        vs += g_vsp[((size_t)p*NBH + bh)*64 + d];
    }
    g_ksum[bh*64 + d]  = ks;
    g_vmean[bh*64 + d] = vs * (1.0f/LL);
}

// ==== Kernel 4: approx QK^T row-max, 32-row warps (SMEM-port optimized) ====
#define M3_QH 0
#define M3_KH 16384
#define M3_KS 32768
#define M3_MB 33024
#define M3_SMEM (M3_MB + 2*128*4)

__global__ __launch_bounds__(256,2) void maxpass2_kernel()
{
    extern __shared__ char smem[];
    const uint32_t sb = smem_u32(smem);
    const int tid = threadIdx.x, wid = tid >> 5, lane = tid & 31;
    const int bh = blockIdx.y, q0 = blockIdx.x * 128;

    if (tid < 64) *(float*)(smem + M3_KS + tid*4) = g_ksum[bh*64 + tid];

    {   // Q tile: 128 rows x 128B, SW128
        const char* qh = (const char*)(g_qh + ((size_t)bh*LL + q0)*64);
        #pragma unroll
        for (int it = 0; it < 4; it++) {
            int byte = (tid + it*256) * 16;
            *(uint4*)(smem + M3_QH + SWZ(byte)) = *(const uint4*)(qh + byte);
        }
    }

    const int qg = wid >> 1, kg = wid & 1;
    const int ag = lane >> 3, ar = lane & 7;
    const int arow0 = qg*32 + ((ag & 1) << 3) + ar;   // mt=0 row base
    const int ahalf = (ag >> 1) << 3;
    const int bm = lane >> 3, brw = lane & 7;
    const int b_nboff = bm >> 1, b_half = (bm & 1) << 3;

    float rmax[2][2];
    rmax[0][0] = rmax[0][1] = rmax[1][0] = rmax[1][1] = -INFINITY;

    for (int kt = 0; kt < LL/128; kt++) {
        __syncthreads();
        {
            const char* kh = (const char*)(g_kh + ((size_t)bh*LL + kt*128)*64);
            #pragma unroll
            for (int it = 0; it < 4; it++) {
                int byte = (tid + it*256) * 16;
                *(uint4*)(smem + M3_KH + SWZ(byte)) = *(const uint4*)(kh + byte);
            }
        }
        __syncthreads();

        float acc[2][8][4];
        #pragma unroll
        for (int mt = 0; mt < 2; mt++)
            #pragma unroll
            for (int nb = 0; nb < 8; nb++)
                #pragma unroll
                for (int j = 0; j < 4; j++) acc[mt][nb][j] = 0.f;

        #pragma unroll
        for (int kc = 0; kc < 4; kc++) {
            uint32_t Ah0[4], Ah1[4];
            ldmA(Ah0, sb + M3_QH + SWZ(arow0*128        + (kc*16 + ahalf)*2));
            ldmA(Ah1, sb + M3_QH + SWZ((arow0+16)*128   + (kc*16 + ahalf)*2));
            #pragma unroll
            for (int nbp = 0; nbp < 8; nbp += 2) {
                uint32_t Bh[4];
                int key = kg*64 + (nbp + b_nboff)*8 + brw;
                ldmB4(Bh, sb + M3_KH + SWZ(key*128 + (kc*16 + b_half)*2));
                mma16816(acc[0][nbp],   Ah0, Bh);
                mma16816(acc[0][nbp+1], Ah0, Bh+2);
                mma16816(acc[1][nbp],   Ah1, Bh);
                mma16816(acc[1][nbp+1], Ah1, Bh+2);
            }
        }
        #pragma unroll
        for (int mt = 0; mt < 2; mt++)
            #pragma unroll
            for (int nb = 0; nb < 8; nb++) {
                rmax[mt][0] = fmaxf(rmax[mt][0], fmaxf(acc[mt][nb][0], acc[mt][nb][1]));
                rmax[mt][1] = fmaxf(rmax[mt][1], fmaxf(acc[mt][nb][2], acc[mt][nb][3]));
            }
    }

    #pragma unroll
    for (int mt = 0; mt < 2; mt++)
        #pragma unroll
        for (int hh = 0; hh < 2; hh++) {
            rmax[mt][hh] = fmaxf(rmax[mt][hh], __shfl_xor_sync(0xffffffffu, rmax[mt][hh], 1));
            rmax[mt][hh] = fmaxf(rmax[mt][hh], __shfl_xor_sync(0xffffffffu, rmax[mt][hh], 2));
        }
    float* mb = (float*)(smem + M3_MB);
    if ((lane & 3) == 0) {
        #pragma unroll
        for (int mt = 0; mt < 2; mt++) {
            int row = qg*32 + mt*16 + (lane >> 2);
            mb[kg*128 + row]     = rmax[mt][0];
            mb[kg*128 + row + 8] = rmax[mt][1];
        }
    }
    __syncthreads();
    if (tid < 128) {
        float m = fmaxf(mb[tid], mb[128 + tid]);
        float dot = 0.f;
        #pragma unroll
        for (int d = 0; d < 64; d++) {
            float qv = __bfloat162float(*(__nv_bfloat16*)(smem + M3_QH + SWZ(tid*128 + d*2)));
            dot = fmaf(qv, *(float*)(smem + M3_KS + d*4), dot);
        }
        g_M[(size_t)bh*LL + q0 + tid] = m - dot * (1.0f/LL);
    }
}

// ========== Kernel 5: top-128 candidates per (b,h) via bitonic sort =========
__global__ __launch_bounds__(256) void topcand_kernel()
{
    const int bh = blockIdx.x, tid = threadIdx.x;
    __shared__ unsigned long long arr[LL];
    for (int i = tid; i < LL; i += 256) {
        uint32_t key = f2ord(g_M[(size_t)bh*LL + i]);
        arr[i] = ((unsigned long long)key << 32) | (uint32_t)i;
    }
    __syncthreads();
    for (int k = 2; k <= LL; k <<= 1) {
        for (int j = k >> 1; j > 0; j >>= 1) {
            for (int i = tid; i < LL; i += 256) {
                int l = i ^ j;
                if (l > i) {
                    unsigned long long a = arr[i], b = arr[l];
                    bool up = ((i & k) == 0);
                    if (up ? (a < b) : (a > b)) { arr[i] = b; arr[l] = a; }
                }
            }
            __syncthreads();
        }
    }
    if (tid < NCAND)
        g_cand[bh*NCAND + tid] = (int)(arr[tid] & 0xFFFFFFFFu);
}

// ===== Kernel 6: exact fp32 Q for candidates: g_qc[bh][c][64] =====
__global__ __launch_bounds__(256) void qcand_kernel(
    const float* __restrict__ x, const float* __restrict__ Wq,
    const float* __restrict__ bq)
{
    const int bh = blockIdx.y, half = blockIdx.x;
    const int b = bh >> 3, h = bh & 7;
    const int tid = threadIdx.x;
    const int d4 = tid & 15, ec = tid >> 4;
    __shared__ float xr[512];
    __shared__ float4 p4[256];

    for (int c = 0; c < 64; c++) {
        int cand = half*64 + c;
        int l = g_cand[bh*NCAND + cand];
        __syncthreads();
        *(float2*)&xr[tid*2] = *(const float2*)&x[((size_t)b*LL + l)*512 + tid*2];
        __syncthreads();

        float4 acc = make_float4(0.f,0.f,0.f,0.f);
        #pragma unroll 8
        for (int e = ec*32; e < ec*32 + 32; e++) {
            float xv = xr[e];
            float4 w = *(const float4*)&Wq[(size_t)e*512 + h*64 + d4*4];
            acc.x = fmaf(xv, w.x, acc.x); acc.y = fmaf(xv, w.y, acc.y);
            acc.z = fmaf(xv, w.z, acc.z); acc.w = fmaf(xv, w.w, acc.w);
        }
        p4[tid] = acc;
        __syncthreads();
        for (int s = 8; s > 0; s >>= 1) {
            if (ec < s) {
                float4 o = p4[tid + s*16];
                acc.x += o.x; acc.y += o.y; acc.z += o.z; acc.w += o.w;
                p4[tid] = acc;
            }
            __syncthreads();
        }
        if (ec == 0) {
            float4 bqv = *(const float4*)&bq[h*64 + d4*4];
            *(float4*)&g_qc[((size_t)bh*NCAND + cand)*64 + d4*4] =
                make_float4(acc.x+bqv.x, acc.y+bqv.y, acc.z+bqv.z, acc.w+bqv.w);
        }
    }
}

// ========== Kernel 7: exact fp32 rescore — tiled GEMM over key splits =======
__global__ __launch_bounds__(256,2) void rescore2_kernel()
{
    extern __shared__ float dsm[];
    float* Qs = dsm;
    float* Ks = dsm + 64*128;
    float* ks = dsm + 2*64*128;

    const int bh = blockIdx.y;
    const int sp = blockIdx.x;
    const int tid = threadIdx.x;
    const int tx  = tid & 15;
    const int ty  = tid >> 4;

    if (tid < 64) ks[tid] = g_ksum[bh*64 + tid];

    #pragma unroll
    for (int it = 0; it < 8; it++) {
        int idx = tid + it*256;
        int cc = idx & 127, d4 = idx >> 7;
        float4 v = *(const float4*)&g_qc[((size_t)bh*NCAND + cc)*64 + d4*4];
        Qs[(4*d4+0)*128 + cc] = v.x; Qs[(4*d4+1)*128 + cc] = v.y;
        Qs[(4*d4+2)*128 + cc] = v.z; Qs[(4*d4+3)*128 + cc] = v.w;
    }

    float rmax[8];
    #pragma unroll
    for (int i = 0; i < 8; i++) rmax[i] = -INFINITY;

    const int kt0 = sp * (LL/128/NSPLIT);
    for (int kt = kt0; kt < kt0 + LL/128/NSPLIT; kt++) {
        __syncthreads();
        #pragma unroll
        for (int it = 0; it < 8; it++) {
            int idx = tid + it*256;
            int ss = idx & 127, d4 = idx >> 7;
            float4 v = *(const float4*)&g_k[((size_t)bh*LL + kt*128 + ss)*64 + d4*4];
            Ks[(4*d4+0)*128 + ss] = v.x; Ks[(4*d4+1)*128 + ss] = v.y;
            Ks[(4*d4+2)*128 + ss] = v.z; Ks[(4*d4+3)*128 + ss] = v.w;
        }
        __syncthreads();

        float acc[8][8];
        #pragma unroll
        for (int i = 0; i < 8; i++)
            #pragma unroll
            for (int j = 0; j < 8; j++) acc[i][j] = 0.f;

        #pragma unroll 4
        for (int kk = 0; kk < 64; kk++) {
            float4 qa = *(float4*)&Qs[kk*128 + ty*8];
            float4 qb = *(float4*)&Qs[kk*128 + ty*8 + 4];
            float4 ka = *(float4*)&Ks[kk*128 + tx*8];
            float4 kb = *(float4*)&Ks[kk*128 + tx*8 + 4];
            float am[8] = {qa.x,qa.y,qa.z,qa.w,qb.x,qb.y,qb.z,qb.w};
            float bm[8] = {ka.x,ka.y,ka.z,ka.w,kb.x,kb.y,kb.z,kb.w};
            #pragma unroll
            for (int i = 0; i < 8; i++)
                #pragma unroll
                for (int j = 0; j < 8; j++)
                    acc[i][j] = fmaf(am[i], bm[j], acc[i][j]);
        }
        #pragma unroll
        for (int i = 0; i < 8; i++) {
            float m = acc[i][0];
            #pragma unroll
            for (int j = 1; j < 8; j++) m = fmaxf(m, acc[i][j]);
            rmax[i] = fmaxf(rmax[i], m);
        }
    }

    float dotv[8];
    #pragma unroll
    for (int i = 0; i < 8; i++) dotv[i] = 0.f;
    if (sp == 0) {
        #pragma unroll
        for (int c = 0; c < 4; c++) {
            float kv = ks[tx*4 + c];
            #pragma unroll
            for (int i = 0; i < 8; i++)
                dotv[i] = fmaf(Qs[(tx*4+c)*128 + ty*8 + i], kv, dotv[i]);
        }
    }
    #pragma unroll
    for (int i = 0; i < 8; i++) {
        float m = rmax[i], dsum = dotv[i];
        #pragma unroll
        for (int off = 8; off > 0; off >>= 1) {
            m    = fmaxf(m, __shfl_xor_sync(0xffffffffu, m, off, 16));
            dsum +=          __shfl_xor_sync(0xffffffffu, dsum, off, 16);
        }
        if (tx == 0) {
            int cc = ty*8 + i;
            g_rmaxp[((size_t)sp*NBH + bh)*NCAND + cc] = m;
            if (sp == 0) g_dotc[bh*NCAND + cc] = dsum;
        }
    }
}

// ========== Kernel 8: combine splits + exact top-40 (slots) ================
__global__ __launch_bounds__(128) void select40_kernel()
{
    const int bh = blockIdx.x, tid = threadIdx.x;
    __shared__ unsigned long long arr[NCAND];
    {
        float m = -INFINITY;
        #pragma unroll
        for (int sp = 0; sp < NSPLIT; sp++)
            m = fmaxf(m, g_rmaxp[((size_t)sp*NBH + bh)*NCAND + tid]);
        float Mex = m - g_dotc[bh*NCAND + tid] * (1.0f/LL);
        arr[tid] = ((unsigned long long)f2ord(Mex) << 32) | (uint32_t)tid;
    }
    __syncthreads();
    for (int k = 2; k <= NCAND; k <<= 1) {
        for (int j = k >> 1; j > 0; j >>= 1) {
            int l = tid ^ j;
            if (l > tid) {
                unsigned long long a = arr[tid], b = arr[l];
                bool up = ((tid & k) == 0);
                if (up ? (a < b) : (a > b)) { arr[tid] = b; arr[l] = a; }
            }
            __syncthreads();
        }
    }
    if (tid < UU)
        g_topslot[bh*UU + tid] = (int)(arr[tid] & 0xFFFFFFFFu);
}

// ===== Kernel 9: flash-style attention, all 40 queries per (bh,split) =======
#define TA_QS 0
#define TA_KT 10240
#define TA_VT (TA_KT + 32768)
#define TA_SC (TA_VT + 32768)
#define TA_IDX (TA_SC + 20480)
#define TA_SMEM (TA_IDX + 256)

__global__ __launch_bounds__(256) void topattn2_kernel()
{
    extern __shared__ char smem[];
    float* qs = (float*)(smem + TA_QS);
    float* Kt = (float*)(smem + TA_KT);
    float* Vt = (float*)(smem + TA_VT);
    float* sc = (float*)(smem + TA_SC);
    int*   idx = (int*)(smem + TA_IDX);

    const int sp = blockIdx.x, bh = blockIdx.y;
    const int tid = threadIdx.x, w = tid >> 5, lane = tid & 31;

    if (tid < UU) idx[tid] = g_topslot[bh*UU + tid];
    __syncthreads();
    for (int i = tid; i < UU*16; i += 256) {
        int r = i >> 4, c = i & 15;
        float4 v = *(const float4*)&g_qc[((size_t)bh*NCAND + idx[r])*64 + c*4];
        qs[r*64 + c*4+0] = v.x*0.125f; qs[r*64 + c*4+1] = v.y*0.125f;
        qs[r*64 + c*4+2] = v.z*0.125f; qs[r*64 + c*4+3] = v.w*0.125f;
    }

    float m[5], l[5], O[5][2];
    #pragma unroll
    for (int qi = 0; qi < 5; qi++) {
        m[qi] = -INFINITY; l[qi] = 0.f; O[qi][0] = 0.f; O[qi][1] = 0.f;
    }

    const int kt0 = sp * (LL/128/NS);
    for (int kt = kt0; kt < kt0 + LL/128/NS; kt++) {
        __syncthreads();
        #pragma unroll
        for (int it = 0; it < 8; it++) {
            int i = tid + it*256;
            int ss = i & 127, d4 = i >> 7;
            float4 v = *(const float4*)&g_k[((size_t)bh*LL + kt*128 + ss)*64 + d4*4];
            Kt[(4*d4+0)*128 + ss] = v.x; Kt[(4*d4+1)*128 + ss] = v.y;
            Kt[(4*d4+2)*128 + ss] = v.z; Kt[(4*d4+3)*128 + ss] = v.w;
        }
        #pragma unroll
        for (int it = 0; it < 8; it++) {
            int i = tid + it*256;
            int ss = i >> 4, c = i & 15;
            *(float4*)&Vt[ss*64 + c*4] =
                *(const float4*)&g_v[((size_t)bh*LL + kt*128 + ss)*64 + c*4];
        }
        __syncthreads();

        float s4[5][4];
        #pragma unroll
        for (int qi = 0; qi < 5; qi++)
            #pragma unroll
            for (int j = 0; j < 4; j++) s4[qi][j] = 0.f;

        #pragma unroll 4
        for (int d = 0; d < 64; d++) {
            float4 kv = *(float4*)&Kt[d*128 + lane*4];
            #pragma unroll
            for (int qi = 0; qi < 5; qi++) {
                float qv = qs[(w*5 + qi)*64 + d];
                s4[qi][0] = fmaf(qv, kv.x, s4[qi][0]);
                s4[qi][1] = fmaf(qv, kv.y, s4[qi][1]);
                s4[qi][2] = fmaf(qv, kv.z, s4[qi][2]);
                s4[qi][3] = fmaf(qv, kv.w, s4[qi][3]);
            }
        }

        float scale[5];
        #pragma unroll
        for (int qi = 0; qi < 5; qi++) {
            float tm = fmaxf(fmaxf(s4[qi][0], s4[qi][1]), fmaxf(s4[qi][2], s4[qi][3]));
            #pragma unroll
            for (int off = 16; off > 0; off >>= 1)
                tm = fmaxf(tm, __shfl_xor_sync(0xffffffffu, tm, off));
            float mn = fmaxf(m[qi], tm);
            scale[qi] = expf(m[qi] - mn);
            float4 p;
            p.x = expf(s4[qi][0] - mn); p.y = expf(s4[qi][1] - mn);
            p.z = expf(s4[qi][2] - mn); p.w = expf(s4[qi][3] - mn);
            *(float4*)&sc[(w*5 + qi)*128 + lane*4] = p;
            float ls = p.x + p.y + p.z + p.w;
            #pragma unroll
            for (int off = 16; off > 0; off >>= 1)
                ls += __shfl_xor_sync(0xffffffffu, ls, off);
            l[qi] = l[qi]*scale[qi] + ls;
            m[qi] = mn;
        }
        __syncwarp();

        #pragma unroll
        for (int qi = 0; qi < 5; qi++) { O[qi][0] *= scale[qi]; O[qi][1] *= scale[qi]; }

        #pragma unroll 4
        for (int s = 0; s < 128; s++) {
            float2 vv = *(float2*)&Vt[s*64 + lane*2];
            #pragma unroll
            for (int qi = 0; qi < 5; qi++) {
                float p = sc[(w*5 + qi)*128 + s];
                O[qi][0] = fmaf(p, vv.x, O[qi][0]);
                O[qi][1] = fmaf(p, vv.y, O[qi][1]);
            }
        }
        __syncwarp();
    }

    #pragma unroll
    for (int qi = 0; qi < 5; qi++) {
        int r = w*5 + qi;
        size_t base = ((size_t)(sp*NBH + bh)*UU + r);
        *(float2*)&g_pO[base*64 + lane*2] = make_float2(O[qi][0], O[qi][1]);
        if (lane == 0) { g_pm[base] = m[qi]; g_pl[base] = l[qi]; }
    }
}

// ================= Kernel 10: decoder tail (per-batch) =================
__global__ __launch_bounds__(256) void final_kernel(
    const float* __restrict__ Wo, const float* __restrict__ bo,
    const float* __restrict__ W1, const float* __restrict__ b1,
    const float* __restrict__ W2, const float* __restrict__ b2,
    const float* __restrict__ ga1, const float* __restrict__ be1,
    const float* __restrict__ ga2, const float* __restrict__ be2,
    const float* __restrict__ Wout, const float* __restrict__ bout,
    float* __restrict__ d_out)
{
    const int b = blockIdx.x, tid = threadIdx.x;
    __shared__ float ctxm[512], av[512], yv[512], ffv[2048], ov[512], red[256];
    __shared__ float wA[HH*UU], wB[HH*UU];
    __shared__ float s_m, s_inv;

    for (int i = tid; i < HH*UU; i += 256) {
        int h = i / UU, r = i % UU;
        size_t b0 = (size_t)(0*NBH + b*HH + h)*UU + r;
        size_t b1i = (size_t)(1*NBH + b*HH + h)*UU + r;
        float m1 = g_pm[b0], m2 = g_pm[b1i];
        float l1 = g_pl[b0], l2 = g_pl[b1i];
        float mm = fmaxf(m1, m2);
        float w1 = expf(m1 - mm), w2 = expf(m2 - mm);
        float den = w1*l1 + w2*l2;
        wA[i] = w1/den; wB[i] = w2/den;
    }
    __syncthreads();

    #pragma unroll
    for (int k = 0; k < 2; k++) {
        int d = tid + k*256;
        int h = d >> 6, dd = d & 63;
        int bh = b*HH + h;
        float val = g_vmean[bh*64 + dd] * (float)(LL - UU);
        for (int r = 0; r < UU; r++) {
            float o1 = g_pO[((size_t)(0*NBH + bh)*UU + r)*64 + dd];
            float o2 = g_pO[((size_t)(1*NBH + bh)*UU + r)*64 + dd];
            val += wA[h*UU + r]*o1 + wB[h*UU + r]*o2;
        }
        ctxm[d] = val * (1.0f/LL);
    }
    __syncthreads();

    #pragma unroll
    for (int k = 0; k < 2; k++) {
        int d = tid + k*256;
        float acc = 0.f;
        for (int e = 0; e < 512; e++)
            acc = fmaf(ctxm[e], Wo[(size_t)e*512 + d], acc);
        av[d] = acc + bo[d];
    }
    __syncthreads();

    red[tid] = 2.f*av[tid] + 2.f*av[tid+256];
    __syncthreads();
    for (int s = 128; s > 0; s >>= 1) { if (tid < s) red[tid] += red[tid+s]; __syncthreads(); }
    if (tid == 0) s_m = red[0] * (1.0f/512.f);
    __syncthreads();
    {
        float t0 = 2.f*av[tid] - s_m, t1 = 2.f*av[tid+256] - s_m;
        red[tid] = t0*t0 + t1*t1;
        __syncthreads();
        for (int s = 128; s > 0; s >>= 1) { if (tid < s) red[tid] += red[tid+s]; __syncthreads(); }
        if (tid == 0) s_inv = 1.0f / sqrtf(red[0]*(1.0f/512.f) + 1e-5f);
        __syncthreads();
        yv[tid]     = t0 * s_inv * ga1[tid]     + be1[tid];
        yv[tid+256] = t1 * s_inv * ga1[tid+256] + be1[tid+256];
    }
    __syncthreads();

    #pragma unroll
    for (int it = 0; it < 8; it++) {
        int f = tid + it*256;
        const float4* wp = (const float4*)&W1[(size_t)f*512];
        float acc = 0.f;
        #pragma unroll 8
        for (int c = 0; c < 128; c++) {
            float4 ww = wp[c];
            acc = fmaf(ww.x, yv[4*c+0], acc);
            acc = fmaf(ww.y, yv[4*c+1], acc);
            acc = fmaf(ww.z, yv[4*c+2], acc);
            acc = fmaf(ww.w, yv[4*c+3], acc);
        }
        ffv[f] = fmaxf(acc + b1[f], 0.f);
    }
    __syncthreads();

    #pragma unroll
    for (int k = 0; k < 2; k++) {
        int d = tid + k*256;
        const float4* wp = (const float4*)&W2[(size_t)d*2048];
        float acc = 0.f;
        #pragma unroll 8
        for (int c = 0; c < 512; c++) {
            float4 ww = wp[c];
            acc = fmaf(ww.x, ffv[4*c+0], acc);
            acc = fmaf(ww.y, ffv[4*c+1], acc);
            acc = fmaf(ww.z, ffv[4*c+2], acc);
            acc = fmaf(ww.w, ffv[4*c+3], acc);
        }
        ov[d] = yv[d] + acc + b2[d];
    }
    __syncthreads();

    red[tid] = ov[tid] + ov[tid+256];
    __syncthreads();
    for (int s = 128; s > 0; s >>= 1) { if (tid < s) red[tid] += red[tid+s]; __syncthreads(); }
    if (tid == 0) s_m = red[0] * (1.0f/512.f);
    __syncthreads();
    {
        float t0 = ov[tid] - s_m, t1 = ov[tid+256] - s_m;
        red[tid] = t0*t0 + t1*t1;
        __syncthreads();
        for (int s = 128; s > 0; s >>= 1) { if (tid < s) red[tid] += red[tid+s]; __syncthreads(); }
        if (tid == 0) s_inv = 1.0f / sqrtf(red[0]*(1.0f/512.f) + 1e-5f);
        __syncthreads();
        float o0 = t0 * s_inv * ga2[tid]     + be2[tid];
        float o1 = t1 * s_inv * ga2[tid+256] + be2[tid+256];
        ov[tid] = o0; ov[tid+256] = o1;
        d_out[BB + (size_t)b*512 + tid]       = o0;
        d_out[BB + (size_t)b*512 + tid + 256] = o1;
    }
    __syncthreads();

    red[tid] = ov[tid]*Wout[tid] + ov[tid+256]*Wout[tid+256];
    __syncthreads();
    for (int s = 128; s > 0; s >>= 1) { if (tid < s) red[tid] += red[tid+s]; __syncthreads(); }
    if (tid == 0) d_out[b] = red[0] + bout[0];
}

// ================= host launcher =================
extern "C" void kernel_launch(void* const* d_in, const int* in_sizes, int n_in,
                              void* d_out, int out_size)
{
    const float* x    = (const float*)d_in[0];
    const float* Wq   = (const float*)d_in[1];
    const float* bq   = (const float*)d_in[2];
    const float* Wk   = (const float*)d_in[3];
    const float* bk   = (const float*)d_in[4];
    const float* Wv   = (const float*)d_in[5];
    const float* bv   = (const float*)d_in[6];
    const float* Wo   = (const float*)d_in[7];
    const float* bo   = (const float*)d_in[8];
    const float* W1   = (const float*)d_in[9];
    const float* b1   = (const float*)d_in[10];
    const float* W2   = (const float*)d_in[11];
    const float* b2   = (const float*)d_in[12];
    const float* ga1  = (const float*)d_in[13];
    const float* be1  = (const float*)d_in[14];
    const float* ga2  = (const float*)d_in[15];
    const float* be2  = (const float*)d_in[16];
    const float* Wout = (const float*)d_in[17];
    const float* bout = (const float*)d_in[18];
    float* out = (float*)d_out;

    const int rs_smem = (2*64*128 + 64) * (int)sizeof(float);
    cudaFuncSetAttribute(maxpass2_kernel,
                         cudaFuncAttributeMaxDynamicSharedMemorySize, M3_SMEM);
    cudaFuncSetAttribute(rescore2_kernel,
                         cudaFuncAttributeMaxDynamicSharedMemorySize, rs_smem);
    cudaFuncSetAttribute(topattn2_kernel,
                         cudaFuncAttributeMaxDynamicSharedMemorySize, TA_SMEM);

    cvt_kernel<<<CVT_XBLKS + 128, 256>>>(x, Wq);
    kv_kernel<<<dim3(128, 8, 2), 256>>>(x, Wk, bk, Wv, bv);
    qproj_kernel<<<dim3(256, 4), 256>>>(bq);
    stats_kernel<<<dim3(NBH, 4), 256>>>();
    statcomb_kernel<<<NBH, 64>>>();
    maxpass2_kernel<<<dim3(LL/128, NBH), 256, M3_SMEM>>>();
    topcand_kernel<<<NBH, 256>>>();
    qcand_kernel<<<dim3(2, NBH), 256>>>(x, Wq, bq);
    rescore2_kernel<<<dim3(NSPLIT, NBH), 256, rs_smem>>>();
    select40_kernel<<<NBH, 128>>>();
    topattn2_kernel<<<dim3(NS, NBH), 256, TA_SMEM>>>();
    final_kernel<<<BB, 256>>>(Wo, bo, W1, b1, W2, b2,
                              ga1, be1, ga2, be2, Wout, bout, out);
}

// round 16
// speedup vs baseline: 1.1381x; 1.0264x over previous
#include <cuda_runtime.h>
#include <cuda_bf16.h>
#include <math.h>
#include <stdint.h>

#define BB 8
#define LL 2048
#define DD 512
#define HH 8
#define DH 64
#define DFF 2048
#define UU 40
#define NCAND 128
#define NSPLIT 4
#define NS 2
#define NBH (BB*HH)

// ---------------- scratch (no allocs allowed) ----------------
__device__ float g_k[NBH*LL*DH];
__device__ float g_v[NBH*LL*DH];
__device__ __nv_bfloat16 g_xh[BB*LL*DD];    // bf16 input
__device__ __nv_bfloat16 g_wqt[DD*DD];      // Wq^T bf16  [n][e]
__device__ __nv_bfloat16 g_qh[NBH*LL*DH];   // bf16 q (approx)
__device__ __nv_bfloat16 g_kh[NBH*LL*DH];   // bf16 k
__device__ float g_M[NBH*LL];
__device__ float g_ksp[4*NBH*DH];           // stats partials
__device__ float g_vsp[4*NBH*DH];
__device__ float g_ksum[NBH*DH];
__device__ float g_vmean[NBH*DH];
__device__ int   g_cand[NBH*NCAND];
__device__ float g_qc[NBH*NCAND*DH];        // exact fp32 q for candidates
__device__ float g_rmaxp[NSPLIT*NBH*NCAND];
__device__ float g_dotc[NBH*NCAND];
__device__ int   g_topslot[NBH*UU];
__device__ float g_pm[NS*NBH*UU];
__device__ float g_pl[NS*NBH*UU];
__device__ float g_pO[NS*NBH*UU*DH];

__device__ __forceinline__ uint32_t smem_u32(const void* p) {
    uint32_t a;
    asm("{ .reg .u64 t; cvta.to.shared.u64 t, %1; cvt.u32.u64 %0, t; }"
        : "=r"(a) : "l"(p));
    return a;
}
#define SWZ(b) ((b) ^ (((b) >> 3) & 0x70))

__device__ __forceinline__ uint32_t f2ord(float f) {
    uint32_t u = __float_as_uint(f);
    return (u & 0x80000000u) ? ~u : (u | 0x80000000u);
}

// packed fp32x2 helpers (FFMA2 — HW dual-issue fp32, ptxas never emits it)
#define FMA_X2(acc, a, b) \
    asm("fma.rn.f32x2 %0, %1, %2, %0;" : "+l"(acc) : "l"(a), "l"(b))
#define PACK_DUP(out, v) \
    asm("mov.b64 %0, {%1, %1};" : "=l"(out) : "r"(__float_as_uint(v)))
#define UNPACK_X2(lo, hi, v) \
    asm("mov.b64 {%0, %1}, %2;" : "=f"(lo), "=f"(hi) : "l"(v))

// ============ Kernel 0: x -> bf16, Wq -> bf16 transposed ============
#define CVT_XBLKS 4096
__global__ __launch_bounds__(256) void cvt_kernel(
    const float* __restrict__ x, const float* __restrict__ Wq)
{
    const int bidx = blockIdx.x, tid = threadIdx.x;
    if (bidx < CVT_XBLKS) {
        size_t base = (size_t)bidx*2048 + tid*8;
        float4 a = *(const float4*)&x[base];
        float4 b = *(const float4*)&x[base+4];
        *(__nv_bfloat162*)&g_xh[base]   = __nv_bfloat162(__float2bfloat16_rn(a.x), __float2bfloat16_rn(a.y));
        *(__nv_bfloat162*)&g_xh[base+2] = __nv_bfloat162(__float2bfloat16_rn(a.z), __float2bfloat16_rn(a.w));
        *(__nv_bfloat162*)&g_xh[base+4] = __nv_bfloat162(__float2bfloat16_rn(b.x), __float2bfloat16_rn(b.y));
        *(__nv_bfloat162*)&g_xh[base+6] = __nv_bfloat162(__float2bfloat16_rn(b.z), __float2bfloat16_rn(b.w));
    } else {
        int i = bidx - CVT_XBLKS;            // 0..127
        int n = i*4 + (tid >> 6);
        int e0 = tid & 63;
        #pragma unroll
        for (int j = 0; j < 8; j++) {
            int e = e0 + 64*j;
            g_wqt[n*512 + e] = __float2bfloat16_rn(Wq[(size_t)e*512 + n]);
        }
    }
}

// ======= Kernel 1: K/V projection (fp32, FFMA2 packed inner loop) ==========
__global__ __launch_bounds__(256) void kv_kernel(
    const float* __restrict__ x,
    const float* __restrict__ Wk, const float* __restrict__ bk,
    const float* __restrict__ Wv, const float* __restrict__ bv)
{
    const int z = blockIdx.z;
    const float* __restrict__ W    = (z==0) ? Wk : Wv;
    const float* __restrict__ bias = (z==0) ? bk : bv;
    float* __restrict__ outp       = (z==0) ? g_k : g_v;

    __shared__ float Xs[16][132];
    __shared__ float Ws[16][68];

    const int m0 = blockIdx.x * 128;
    const int n0 = blockIdx.y * 64;
    const int tid = threadIdx.x;
    const int tn = tid & 15;
    const int tm = tid >> 4;

    unsigned long long acc2[4][4];     // [m-pair][n], each holds rows (2i2, 2i2+1)
    #pragma unroll
    for (int i2 = 0; i2 < 4; i2++)
        #pragma unroll
        for (int j = 0; j < 4; j++) acc2[i2][j] = 0ull;

    for (int k0 = 0; k0 < 512; k0 += 16) {
        #pragma unroll
        for (int it = 0; it < 2; it++) {
            int idx = tid + it*256;
            int r = idx >> 2, c = idx & 3;
            float4 xv = *(const float4*)&x[(size_t)(m0 + r)*512 + k0 + c*4];
            Xs[c*4+0][r] = xv.x; Xs[c*4+1][r] = xv.y;
            Xs[c*4+2][r] = xv.z; Xs[c*4+3][r] = xv.w;
        }
        {
            int r = tid >> 4, c = tid & 15;
            float4 wv = *(const float4*)&W[(size_t)(k0 + r)*512 + n0 + c*4];
            *(float4*)&Ws[r][c*4] = wv;
        }
        __syncthreads();
        #pragma unroll
        for (int kk = 0; kk < 16; kk++) {
            const unsigned long long* ap =
                (const unsigned long long*)&Xs[kk][tm*8];   // 8B-aligned m-pairs
            unsigned long long a2_0 = ap[0], a2_1 = ap[1];
            unsigned long long a2_2 = ap[2], a2_3 = ap[3];
            float4 b0 = *(float4*)&Ws[kk][tn*4];
            unsigned long long bd[4];
            PACK_DUP(bd[0], b0.x); PACK_DUP(bd[1], b0.y);
            PACK_DUP(bd[2], b0.z); PACK_DUP(bd[3], b0.w);
            #pragma unroll
            for (int j = 0; j < 4; j++) {
                FMA_X2(acc2[0][j], a2_0, bd[j]);
                FMA_X2(acc2[1][j], a2_1, bd[j]);
                FMA_X2(acc2[2][j], a2_2, bd[j]);
                FMA_X2(acc2[3][j], a2_3, bd[j]);
            }
        }
        __syncthreads();
    }

    // unpack to scalar accumulators
    float acc[8][4];
    #pragma unroll
    for (int i2 = 0; i2 < 4; i2++)
        #pragma unroll
        for (int j = 0; j < 4; j++) {
            float lo, hi;
            UNPACK_X2(lo, hi, acc2[i2][j]);
            acc[2*i2][j]   = lo;
            acc[2*i2+1][j] = hi;
        }

    const int h = n0 >> 6;
    float4 b4 = *(const float4*)&bias[n0 + tn*4];
    #pragma unroll
    for (int i = 0; i < 8; i++) {
        int r  = m0 + tm*8 + i;
        int bb = r >> 11, l = r & 2047;
        size_t base = ((size_t)(bb*HH + h)*LL + l)*64 + tn*4;
        float o[4] = {acc[i][0]+b4.x, acc[i][1]+b4.y, acc[i][2]+b4.z, acc[i][3]+b4.w};
        *(float4*)&outp[base] = make_float4(o[0],o[1],o[2],o[3]);
        if (z == 0) {
            *(__nv_bfloat162*)&g_kh[base]   =
                __nv_bfloat162(__float2bfloat16_rn(o[0]), __float2bfloat16_rn(o[1]));
            *(__nv_bfloat162*)&g_kh[base+2] =
                __nv_bfloat162(__float2bfloat16_rn(o[2]), __float2bfloat16_rn(o[3]));
        }
    }
}

// ---------------- mma helpers ----------------
__device__ __forceinline__ void ldmA(uint32_t* a, uint32_t addr) {
    asm volatile("ldmatrix.sync.aligned.m8n8.x4.shared.b16 {%0,%1,%2,%3}, [%4];"
        : "=r"(a[0]),"=r"(a[1]),"=r"(a[2]),"=r"(a[3]) : "r"(addr));
}
__device__ __forceinline__ void ldmB4(uint32_t* b, uint32_t addr) {
    asm volatile("ldmatrix.sync.aligned.m8n8.x4.shared.b16 {%0,%1,%2,%3}, [%4];"
        : "=r"(b[0]),"=r"(b[1]),"=r"(b[2]),"=r"(b[3]) : "r"(addr));
}
__device__ __forceinline__ void mma16816(float* c, const uint32_t* a, const uint32_t* b) {
    asm volatile(
        "mma.sync.aligned.m16n8k16.row.col.f32.bf16.bf16.f32 "
        "{%0,%1,%2,%3}, {%4,%5,%6,%7}, {%8,%9}, {%0,%1,%2,%3};"
        : "+f"(c[0]),"+f"(c[1]),"+f"(c[2]),"+f"(c[3])
        : "r"(a[0]),"r"(a[1]),"r"(a[2]),"r"(a[3]), "r"(b[0]),"r"(b[1]));
}

// ===== Kernel 2: Q projection in bf16 HMMA: g_qh = bf16(Xh @ WqT^T + bq) ====
#define QP_A 0
#define QP_B 8192
__global__ __launch_bounds__(256) void qproj_kernel(const float* __restrict__ bq)
{
    __shared__ char smem[24576];
    const uint32_t sb = smem_u32(smem);
    const int tid = threadIdx.x, wid = tid >> 5, lane = tid & 31;
    const int m0 = blockIdx.x * 64, n0 = blockIdx.y * 128;

    const int qg = wid >> 1, kg = wid & 1;
    const int ag = lane >> 3, ar = lane & 7;
    const int arow  = qg*16 + ((ag & 1) << 3) + ar;
    const int ahalf = (ag >> 1) << 3;
    const int bm = lane >> 3, brw = lane & 7;
    const int b_nboff = bm >> 1, b_half = (bm & 1) << 3;

    float acc[8][4];
    #pragma unroll
    for (int nb = 0; nb < 8; nb++)
        #pragma unroll
        for (int j = 0; j < 4; j++) acc[nb][j] = 0.f;

    for (int kc0 = 0; kc0 < 8; kc0++) {
        __syncthreads();
        #pragma unroll
        for (int it = 0; it < 2; it++) {
            int i = tid + it*256;
            int row = i >> 3, c = i & 7;
            const char* ap = (const char*)(g_xh + (size_t)(m0+row)*512 + kc0*64);
            *(uint4*)(smem + QP_A + SWZ(row*128 + c*16)) = *(const uint4*)(ap + c*16);
        }
        #pragma unroll
        for (int it = 0; it < 4; it++) {
            int i = tid + it*256;
            int row = i >> 3, c = i & 7;
            const char* bp = (const char*)(g_wqt + (size_t)(n0+row)*512 + kc0*64);
            *(uint4*)(smem + QP_B + SWZ(row*128 + c*16)) = *(const uint4*)(bp + c*16);
        }
        __syncthreads();

        #pragma unroll
        for (int kc = 0; kc < 4; kc++) {
            uint32_t Ah[4];
            ldmA(Ah, sb + QP_A + SWZ(arow*128 + (kc*16 + ahalf)*2));
            #pragma unroll
            for (int nbp = 0; nbp < 8; nbp += 2) {
                uint32_t Bh[4];
                int nrow = kg*64 + (nbp + b_nboff)*8 + brw;
                ldmB4(Bh, sb + QP_B + SWZ(nrow*128 + (kc*16 + b_half)*2));
                mma16816(acc[nbp],   Ah, Bh);
                mma16816(acc[nbp+1], Ah, Bh+2);
            }
        }
    }

    const int r_lo = m0 + qg*16 + (lane >> 2);
    const int colb = (lane & 3) * 2;
    #pragma unroll
    for (int nb = 0; nb < 8; nb++) {
        int n = n0 + kg*64 + nb*8 + colb;
        int h = n >> 6, d = n & 63;
        float2 bq2 = *(const float2*)&bq[n];
        #pragma unroll
        for (int rr = 0; rr < 2; rr++) {
            int m = r_lo + rr*8;
            int bb = m >> 11, l = m & 2047;
            float v0 = acc[nb][rr*2+0] + bq2.x;
            float v1 = acc[nb][rr*2+1] + bq2.y;
            *(__nv_bfloat162*)&g_qh[((size_t)(bb*HH + h)*LL + l)*64 + d] =
                __nv_bfloat162(__float2bfloat16_rn(v0), __float2bfloat16_rn(v1));
        }
    }
}

// ========== Kernel 3: key-sum & value-mean (4-way split + combine) =========
__global__ __launch_bounds__(256) void stats_kernel()
{
    const int bh = blockIdx.x, p4 = blockIdx.y;
    const int tid = threadIdx.x;
    const int d4 = tid & 15, r = tid >> 4;

    const float4* kp = (const float4*)(g_k + ((size_t)bh*LL + p4*512 + r*32)*64);
    const float4* vp = (const float4*)(g_v + ((size_t)bh*LL + p4*512 + r*32)*64);
    float4 ks = make_float4(0,0,0,0), vs = make_float4(0,0,0,0);
    #pragma unroll 4
    for (int s = 0; s < 32; s++) {
        float4 a = kp[s*16 + d4];
        float4 b = vp[s*16 + d4];
        ks.x += a.x; ks.y += a.y; ks.z += a.z; ks.w += a.w;
        vs.x += b.x; vs.y += b.y; vs.z += b.z; vs.w += b.w;
    }
    __shared__ float4 sk[256], sv[256];
    sk[tid] = ks; sv[tid] = vs;
    __syncthreads();
    for (int s = 8; s > 0; s >>= 1) {
        if (r < s) {
            float4 a = sk[tid + s*16], b = sv[tid + s*16];
            ks.x += a.x; ks.y += a.y; ks.z += a.z; ks.w += a.w;
            vs.x += b.x; vs.y += b.y; vs.z += b.z; vs.w += b.w;
            sk[tid] = ks; sv[tid] = vs;
        }
        __syncthreads();
    }
    if (r == 0) {
        *(float4*)&g_ksp[((size_t)p4*NBH + bh)*64 + d4*4] = ks;
        *(float4*)&g_vsp[((size_t)p4*NBH + bh)*64 + d4*4] = vs;
    }
}

__global__ __launch_bounds__(64) void statcomb_kernel()
{
    const int bh = blockIdx.x, d = threadIdx.x;
    float ks = 0.f, vs = 0.f;
    #pragma unroll
    for (int p = 0; p < 4; p++) {
        ks += g_ksp[((size_t)p*NBH + bh)*64 + d];
        vs += g_vsp[((size_t)p*NBH + bh)*64 + d];
    }
    g_ksum[bh*64 + d]  = ks;
    g_vmean[bh*64 + d] = vs * (1.0f/LL);
}

// ==== Kernel 4: approx QK^T row-max, 32-row warps ====
#define M3_QH 0
#define M3_KH 16384
#define M3_KS 32768
#define M3_MB 33024
#define M3_SMEM (M3_MB + 2*128*4)

__global__ __launch_bounds__(256,2) void maxpass2_kernel()
{
    extern __shared__ char smem[];
    const uint32_t sb = smem_u32(smem);
    const int tid = threadIdx.x, wid = tid >> 5, lane = tid & 31;
    const int bh = blockIdx.y, q0 = blockIdx.x * 128;

    if (tid < 64) *(float*)(smem + M3_KS + tid*4) = g_ksum[bh*64 + tid];

    {   // Q tile: 128 rows x 128B, SW128
        const char* qh = (const char*)(g_qh + ((size_t)bh*LL + q0)*64);
        #pragma unroll
        for (int it = 0; it < 4; it++) {
            int byte = (tid + it*256) * 16;
            *(uint4*)(smem + M3_QH + SWZ(byte)) = *(const uint4*)(qh + byte);
        }
    }

    const int qg = wid >> 1, kg = wid & 1;
    const int ag = lane >> 3, ar = lane & 7;
    const int arow0 = qg*32 + ((ag & 1) << 3) + ar;
    const int ahalf = (ag >> 1) << 3;
    const int bm = lane >> 3, brw = lane & 7;
    const int b_nboff = bm >> 1, b_half = (bm & 1) << 3;

    float rmax[2][2];
    rmax[0][0] = rmax[0][1] = rmax[1][0] = rmax[1][1] = -INFINITY;

    for (int kt = 0; kt < LL/128; kt++) {
        __syncthreads();
        {
            const char* kh = (const char*)(g_kh + ((size_t)bh*LL + kt*128)*64);
            #pragma unroll
            for (int it = 0; it < 4; it++) {
                int byte = (tid + it*256) * 16;
                *(uint4*)(smem + M3_KH + SWZ(byte)) = *(const uint4*)(kh + byte);
            }
        }
        __syncthreads();

        float acc[2][8][4];
        #pragma unroll
        for (int mt = 0; mt < 2; mt++)
            #pragma unroll
            for (int nb = 0; nb < 8; nb++)
                #pragma unroll
                for (int j = 0; j < 4; j++) acc[mt][nb][j] = 0.f;

        #pragma unroll
        for (int kc = 0; kc < 4; kc++) {
            uint32_t Ah0[4], Ah1[4];
            ldmA(Ah0, sb + M3_QH + SWZ(arow0*128        + (kc*16 + ahalf)*2));
            ldmA(Ah1, sb + M3_QH + SWZ((arow0+16)*128   + (kc*16 + ahalf)*2));
            #pragma unroll
            for (int nbp = 0; nbp < 8; nbp += 2) {
                uint32_t Bh[4];
                int key = kg*64 + (nbp + b_nboff)*8 + brw;
                ldmB4(Bh, sb + M3_KH + SWZ(key*128 + (kc*16 + b_half)*2));
                mma16816(acc[0][nbp],   Ah0, Bh);
                mma16816(acc[0][nbp+1], Ah0, Bh+2);
                mma16816(acc[1][nbp],   Ah1, Bh);
                mma16816(acc[1][nbp+1], Ah1, Bh+2);
            }
        }
        #pragma unroll
        for (int mt = 0; mt < 2; mt++)
            #pragma unroll
            for (int nb = 0; nb < 8; nb++) {
                rmax[mt][0] = fmaxf(rmax[mt][0], fmaxf(acc[mt][nb][0], acc[mt][nb][1]));
                rmax[mt][1] = fmaxf(rmax[mt][1], fmaxf(acc[mt][nb][2], acc[mt][nb][3]));
            }
    }

    #pragma unroll
    for (int mt = 0; mt < 2; mt++)
        #pragma unroll
        for (int hh = 0; hh < 2; hh++) {
            rmax[mt][hh] = fmaxf(rmax[mt][hh], __shfl_xor_sync(0xffffffffu, rmax[mt][hh], 1));
            rmax[mt][hh] = fmaxf(rmax[mt][hh], __shfl_xor_sync(0xffffffffu, rmax[mt][hh], 2));
        }
    float* mb = (float*)(smem + M3_MB);
    if ((lane & 3) == 0) {
        #pragma unroll
        for (int mt = 0; mt < 2; mt++) {
            int row = qg*32 + mt*16 + (lane >> 2);
            mb[kg*128 + row]     = rmax[mt][0];
            mb[kg*128 + row + 8] = rmax[mt][1];
        }
    }
    __syncthreads();
    if (tid < 128) {
        float m = fmaxf(mb[tid], mb[128 + tid]);
        float dot = 0.f;
        #pragma unroll
        for (int d = 0; d < 64; d++) {
            float qv = __bfloat162float(*(__nv_bfloat16*)(smem + M3_QH + SWZ(tid*128 + d*2)));
            dot = fmaf(qv, *(float*)(smem + M3_KS + d*4), dot);
        }
        g_M[(size_t)bh*LL + q0 + tid] = m - dot * (1.0f/LL);
    }
}

// ========== Kernel 5: top-128 candidates per (b,h) via bitonic sort =========
__global__ __launch_bounds__(256) void topcand_kernel()
{
    const int bh = blockIdx.x, tid = threadIdx.x;
    __shared__ unsigned long long arr[LL];
    for (int i = tid; i < LL; i += 256) {
        uint32_t key = f2ord(g_M[(size_t)bh*LL + i]);
        arr[i] = ((unsigned long long)key << 32) | (uint32_t)i;
    }
    __syncthreads();
    for (int k = 2; k <= LL; k <<= 1) {
        for (int j = k >> 1; j > 0; j >>= 1) {
            for (int i = tid; i < LL; i += 256) {
                int l = i ^ j;
                if (l > i) {
                    unsigned long long a = arr[i], b = arr[l];
                    bool up = ((i & k) == 0);
                    if (up ? (a < b) : (a > b)) { arr[i] = b; arr[l] = a; }
                }
            }
            __syncthreads();
        }
    }
    if (tid < NCAND)
        g_cand[bh*NCAND + tid] = (int)(arr[tid] & 0xFFFFFFFFu);
}

// ===== Kernel 6: exact fp32 Q for candidates: g_qc[bh][c][64] =====
__global__ __launch_bounds__(256) void qcand_kernel(
    const float* __restrict__ x, const float* __restrict__ Wq,
    const float* __restrict__ bq)
{
    const int bh = blockIdx.y, half = blockIdx.x;
    const int b = bh >> 3, h = bh & 7;
    const int tid = threadIdx.x;
    const int d4 = tid & 15, ec = tid >> 4;
    __shared__ float xr[512];
    __shared__ float4 p4[256];

    for (int c = 0; c < 64; c++) {
        int cand = half*64 + c;
        int l = g_cand[bh*NCAND + cand];
        __syncthreads();
        *(float2*)&xr[tid*2] = *(const float2*)&x[((size_t)b*LL + l)*512 + tid*2];
        __syncthreads();

        float4 acc = make_float4(0.f,0.f,0.f,0.f);
        #pragma unroll 8
        for (int e = ec*32; e < ec*32 + 32; e++) {
            float xv = xr[e];
            float4 w = *(const float4*)&Wq[(size_t)e*512 + h*64 + d4*4];
            acc.x = fmaf(xv, w.x, acc.x); acc.y = fmaf(xv, w.y, acc.y);
            acc.z = fmaf(xv, w.z, acc.z); acc.w = fmaf(xv, w.w, acc.w);
        }
        p4[tid] = acc;
        __syncthreads();
        for (int s = 8; s > 0; s >>= 1) {
            if (ec < s) {
                float4 o = p4[tid + s*16];
                acc.x += o.x; acc.y += o.y; acc.z += o.z; acc.w += o.w;
                p4[tid] = acc;
            }
            __syncthreads();
        }
        if (ec == 0) {
            float4 bqv = *(const float4*)&bq[h*64 + d4*4];
            *(float4*)&g_qc[((size_t)bh*NCAND + cand)*64 + d4*4] =
                make_float4(acc.x+bqv.x, acc.y+bqv.y, acc.z+bqv.z, acc.w+bqv.w);
        }
    }
}

// ========== Kernel 7: exact fp32 rescore — tiled GEMM over key splits =======
__global__ __launch_bounds__(256,2) void rescore2_kernel()
{
    extern __shared__ float dsm[];
    float* Qs = dsm;
    float* Ks = dsm + 64*128;
    float* ks = dsm + 2*64*128;

    const int bh = blockIdx.y;
    const int sp = blockIdx.x;
    const int tid = threadIdx.x;
    const int tx  = tid & 15;
    const int ty  = tid >> 4;

    if (tid < 64) ks[tid] = g_ksum[bh*64 + tid];

    #pragma unroll
    for (int it = 0; it < 8; it++) {
        int idx = tid + it*256;
        int cc = idx & 127, d4 = idx >> 7;
        float4 v = *(const float4*)&g_qc[((size_t)bh*NCAND + cc)*64 + d4*4];
        Qs[(4*d4+0)*128 + cc] = v.x; Qs[(4*d4+1)*128 + cc] = v.y;
        Qs[(4*d4+2)*128 + cc] = v.z; Qs[(4*d4+3)*128 + cc] = v.w;
    }

    float rmax[8];
    #pragma unroll
    for (int i = 0; i < 8; i++) rmax[i] = -INFINITY;

    const int kt0 = sp * (LL/128/NSPLIT);
    for (int kt = kt0; kt < kt0 + LL/128/NSPLIT; kt++) {
        __syncthreads();
        #pragma unroll
        for (int it = 0; it < 8; it++) {
            int idx = tid + it*256;
            int ss = idx & 127, d4 = idx >> 7;
            float4 v = *(const float4*)&g_k[((size_t)bh*LL + kt*128 + ss)*64 + d4*4];
            Ks[(4*d4+0)*128 + ss] = v.x; Ks[(4*d4+1)*128 + ss] = v.y;
            Ks[(4*d4+2)*128 + ss] = v.z; Ks[(4*d4+3)*128 + ss] = v.w;
        }
        __syncthreads();

        float acc[8][8];
        #pragma unroll
        for (int i = 0; i < 8; i++)
            #pragma unroll
            for (int j = 0; j < 8; j++) acc[i][j] = 0.f;

        #pragma unroll 4
        for (int kk = 0; kk < 64; kk++) {
            float4 qa = *(float4*)&Qs[kk*128 + ty*8];
            float4 qb = *(float4*)&Qs[kk*128 + ty*8 + 4];
            float4 ka = *(float4*)&Ks[kk*128 + tx*8];
            float4 kb = *(float4*)&Ks[kk*128 + tx*8 + 4];
            float am[8] = {qa.x,qa.y,qa.z,qa.w,qb.x,qb.y,qb.z,qb.w};
            float bm[8] = {ka.x,ka.y,ka.z,ka.w,kb.x,kb.y,kb.z,kb.w};
            #pragma unroll
            for (int i = 0; i < 8; i++)
                #pragma unroll
                for (int j = 0; j < 8; j++)
                    acc[i][j] = fmaf(am[i], bm[j], acc[i][j]);
        }
        #pragma unroll
        for (int i = 0; i < 8; i++) {
            float m = acc[i][0];
            #pragma unroll
            for (int j = 1; j < 8; j++) m = fmaxf(m, acc[i][j]);
            rmax[i] = fmaxf(rmax[i], m);
        }
    }

    float dotv[8];
    #pragma unroll
    for (int i = 0; i < 8; i++) dotv[i] = 0.f;
    if (sp == 0) {
        #pragma unroll
        for (int c = 0; c < 4; c++) {
            float kv = ks[tx*4 + c];
            #pragma unroll
            for (int i = 0; i < 8; i++)
                dotv[i] = fmaf(Qs[(tx*4+c)*128 + ty*8 + i], kv, dotv[i]);
        }
    }
    #pragma unroll
    for (int i = 0; i < 8; i++) {
        float m = rmax[i], dsum = dotv[i];
        #pragma unroll
        for (int off = 8; off > 0; off >>= 1) {
            m    = fmaxf(m, __shfl_xor_sync(0xffffffffu, m, off, 16));
            dsum +=          __shfl_xor_sync(0xffffffffu, dsum, off, 16);
        }
        if (tx == 0) {
            int cc = ty*8 + i;
            g_rmaxp[((size_t)sp*NBH + bh)*NCAND + cc] = m;
            if (sp == 0) g_dotc[bh*NCAND + cc] = dsum;
        }
    }
}

// ========== Kernel 8: combine splits + exact top-40 (slots) ================
__global__ __launch_bounds__(128) void select40_kernel()
{
    const int bh = blockIdx.x, tid = threadIdx.x;
    __shared__ unsigned long long arr[NCAND];
    {
        float m = -INFINITY;
        #pragma unroll
        for (int sp = 0; sp < NSPLIT; sp++)
            m = fmaxf(m, g_rmaxp[((size_t)sp*NBH + bh)*NCAND + tid]);
        float Mex = m - g_dotc[bh*NCAND + tid] * (1.0f/LL);
        arr[tid] = ((unsigned long long)f2ord(Mex) << 32) | (uint32_t)tid;
    }
    __syncthreads();
    for (int k = 2; k <= NCAND; k <<= 1) {
        for (int j = k >> 1; j > 0; j >>= 1) {
            int l = tid ^ j;
            if (l > tid) {
                unsigned long long a = arr[tid], b = arr[l];
                bool up = ((tid & k) == 0);
                if (up ? (a < b) : (a > b)) { arr[tid] = b; arr[l] = a; }
            }
            __syncthreads();
        }
    }
    if (tid < UU)
        g_topslot[bh*UU + tid] = (int)(arr[tid] & 0xFFFFFFFFu);
}

// ===== Kernel 9: flash-style attention, all 40 queries per (bh,split) =======
#define TA_QS 0
#define TA_KT 10240
#define TA_VT (TA_KT + 32768)
#define TA_SC (TA_VT + 32768)
#define TA_IDX (TA_SC + 20480)
#define TA_SMEM (TA_IDX + 256)

__global__ __launch_bounds__(256) void topattn2_kernel()
{
    extern __shared__ char smem[];
    float* qs = (float*)(smem + TA_QS);
    float* Kt = (float*)(smem + TA_KT);
    float* Vt = (float*)(smem + TA_VT);
    float* sc = (float*)(smem + TA_SC);
    int*   idx = (int*)(smem + TA_IDX);

    const int sp = blockIdx.x, bh = blockIdx.y;
    const int tid = threadIdx.x, w = tid >> 5, lane = tid & 31;

    if (tid < UU) idx[tid] = g_topslot[bh*UU + tid];
    __syncthreads();
    for (int i = tid; i < UU*16; i += 256) {
        int r = i >> 4, c = i & 15;
        float4 v = *(const float4*)&g_qc[((size_t)bh*NCAND + idx[r])*64 + c*4];
        qs[r*64 + c*4+0] = v.x*0.125f; qs[r*64 + c*4+1] = v.y*0.125f;
        qs[r*64 + c*4+2] = v.z*0.125f; qs[r*64 + c*4+3] = v.w*0.125f;
    }

    float m[5], l[5], O[5][2];
    #pragma unroll
    for (int qi = 0; qi < 5; qi++) {
        m[qi] = -INFINITY; l[qi] = 0.f; O[qi][0] = 0.f; O[qi][1] = 0.f;
    }

    const int kt0 = sp * (LL/128/NS);
    for (int kt = kt0; kt < kt0 + LL/128/NS; kt++) {
        __syncthreads();
        #pragma unroll
        for (int it = 0; it < 8; it++) {
            int i = tid + it*256;
            int ss = i & 127, d4 = i >> 7;
            float4 v = *(const float4*)&g_k[((size_t)bh*LL + kt*128 + ss)*64 + d4*4];
            Kt[(4*d4+0)*128 + ss] = v.x; Kt[(4*d4+1)*128 + ss] = v.y;
            Kt[(4*d4+2)*128 + ss] = v.z; Kt[(4*d4+3)*128 + ss] = v.w;
        }
        #pragma unroll
        for (int it = 0; it < 8; it++) {
            int i = tid + it*256;
            int ss = i >> 4, c = i & 15;
            *(float4*)&Vt[ss*64 + c*4] =
                *(const float4*)&g_v[((size_t)bh*LL + kt*128 + ss)*64 + c*4];
        }
        __syncthreads();

        float s4[5][4];
        #pragma unroll
        for (int qi = 0; qi < 5; qi++)
            #pragma unroll
            for (int j = 0; j < 4; j++) s4[qi][j] = 0.f;

        #pragma unroll 4
        for (int d = 0; d < 64; d++) {
            float4 kv = *(float4*)&Kt[d*128 + lane*4];
            #pragma unroll
            for (int qi = 0; qi < 5; qi++) {
                float qv = qs[(w*5 + qi)*64 + d];
                s4[qi][0] = fmaf(qv, kv.x, s4[qi][0]);
                s4[qi][1] = fmaf(qv, kv.y, s4[qi][1]);
                s4[qi][2] = fmaf(qv, kv.z, s4[qi][2]);
                s4[qi][3] = fmaf(qv, kv.w, s4[qi][3]);
            }
        }

        float scale[5];
        #pragma unroll
        for (int qi = 0; qi < 5; qi++) {
            float tm = fmaxf(fmaxf(s4[qi][0], s4[qi][1]), fmaxf(s4[qi][2], s4[qi][3]));
            #pragma unroll
            for (int off = 16; off > 0; off >>= 1)
                tm = fmaxf(tm, __shfl_xor_sync(0xffffffffu, tm, off));
            float mn = fmaxf(m[qi], tm);
            scale[qi] = expf(m[qi] - mn);
            float4 p;
            p.x = expf(s4[qi][0] - mn); p.y = expf(s4[qi][1] - mn);
            p.z = expf(s4[qi][2] - mn); p.w = expf(s4[qi][3] - mn);
            *(float4*)&sc[(w*5 + qi)*128 + lane*4] = p;
            float ls = p.x + p.y + p.z + p.w;
            #pragma unroll
            for (int off = 16; off > 0; off >>= 1)
                ls += __shfl_xor_sync(0xffffffffu, ls, off);
            l[qi] = l[qi]*scale[qi] + ls;
            m[qi] = mn;
        }
        __syncwarp();

        #pragma unroll
        for (int qi = 0; qi < 5; qi++) { O[qi][0] *= scale[qi]; O[qi][1] *= scale[qi]; }

        #pragma unroll 4
        for (int s = 0; s < 128; s++) {
            float2 vv = *(float2*)&Vt[s*64 + lane*2];
            #pragma unroll
            for (int qi = 0; qi < 5; qi++) {
                float p = sc[(w*5 + qi)*128 + s];
                O[qi][0] = fmaf(p, vv.x, O[qi][0]);
                O[qi][1] = fmaf(p, vv.y, O[qi][1]);
            }
        }
        __syncwarp();
    }

    #pragma unroll
    for (int qi = 0; qi < 5; qi++) {
        int r = w*5 + qi;
        size_t base = ((size_t)(sp*NBH + bh)*UU + r);
        *(float2*)&g_pO[base*64 + lane*2] = make_float2(O[qi][0], O[qi][1]);
        if (lane == 0) { g_pm[base] = m[qi]; g_pl[base] = l[qi]; }
    }
}

// ================= Kernel 10: decoder tail (per-batch) =================
__global__ __launch_bounds__(256) void final_kernel(
    const float* __restrict__ Wo, const float* __restrict__ bo,
    const float* __restrict__ W1, const float* __restrict__ b1,
    const float* __restrict__ W2, const float* __restrict__ b2,
    const float* __restrict__ ga1, const float* __restrict__ be1,
    const float* __restrict__ ga2, const float* __restrict__ be2,
    const float* __restrict__ Wout, const float* __restrict__ bout,
    float* __restrict__ d_out)
{
    const int b = blockIdx.x, tid = threadIdx.x;
    __shared__ float ctxm[512], av[512], yv[512], ffv[2048], ov[512], red[256];
    __shared__ float wA[HH*UU], wB[HH*UU];
    __shared__ float s_m, s_inv;

    for (int i = tid; i < HH*UU; i += 256) {
        int h = i / UU, r = i % UU;
        size_t b0 = (size_t)(0*NBH + b*HH + h)*UU + r;
        size_t b1i = (size_t)(1*NBH + b*HH + h)*UU + r;
        float m1 = g_pm[b0], m2 = g_pm[b1i];
        float l1 = g_pl[b0], l2 = g_pl[b1i];
        float mm = fmaxf(m1, m2);
        float w1 = expf(m1 - mm), w2 = expf(m2 - mm);
        float den = w1*l1 + w2*l2;
        wA[i] = w1/den; wB[i] = w2/den;
    }
    __syncthreads();

    #pragma unroll
    for (int k = 0; k < 2; k++) {
        int d = tid + k*256;
        int h = d >> 6, dd = d & 63;
        int bh = b*HH + h;
        float val = g_vmean[bh*64 + dd] * (float)(LL - UU);
        for (int r = 0; r < UU; r++) {
            float o1 = g_pO[((size_t)(0*NBH + bh)*UU + r)*64 + dd];
            float o2 = g_pO[((size_t)(1*NBH + bh)*UU + r)*64 + dd];
            val += wA[h*UU + r]*o1 + wB[h*UU + r]*o2;
        }
        ctxm[d] = val * (1.0f/LL);
    }
    __syncthreads();

    #pragma unroll
    for (int k = 0; k < 2; k++) {
        int d = tid + k*256;
        float acc = 0.f;
        for (int e = 0; e < 512; e++)
            acc = fmaf(ctxm[e], Wo[(size_t)e*512 + d], acc);
        av[d] = acc + bo[d];
    }
    __syncthreads();

    red[tid] = 2.f*av[tid] + 2.f*av[tid+256];
    __syncthreads();
    for (int s = 128; s > 0; s >>= 1) { if (tid < s) red[tid] += red[tid+s]; __syncthreads(); }
    if (tid == 0) s_m = red[0] * (1.0f/512.f);
    __syncthreads();
    {
        float t0 = 2.f*av[tid] - s_m, t1 = 2.f*av[tid+256] - s_m;
        red[tid] = t0*t0 + t1*t1;
        __syncthreads();
        for (int s = 128; s > 0; s >>= 1) { if (tid < s) red[tid] += red[tid+s]; __syncthreads(); }
        if (tid == 0) s_inv = 1.0f / sqrtf(red[0]*(1.0f/512.f) + 1e-5f);
        __syncthreads();
        yv[tid]     = t0 * s_inv * ga1[tid]     + be1[tid];
        yv[tid+256] = t1 * s_inv * ga1[tid+256] + be1[tid+256];
    }
    __syncthreads();

    #pragma unroll
    for (int it = 0; it < 8; it++) {
        int f = tid + it*256;
        const float4* wp = (const float4*)&W1[(size_t)f*512];
        float acc = 0.f;
        #pragma unroll 8
        for (int c = 0; c < 128; c++) {
            float4 ww = wp[c];
            acc = fmaf(ww.x, yv[4*c+0], acc);
            acc = fmaf(ww.y, yv[4*c+1], acc);
            acc = fmaf(ww.z, yv[4*c+2], acc);
            acc = fmaf(ww.w, yv[4*c+3], acc);
        }
        ffv[f] = fmaxf(acc + b1[f], 0.f);
    }
    __syncthreads();

    #pragma unroll
    for (int k = 0; k < 2; k++) {
        int d = tid + k*256;
        const float4* wp = (const float4*)&W2[(size_t)d*2048];
        float acc = 0.f;
        #pragma unroll 8
        for (int c = 0; c < 512; c++) {
            float4 ww = wp[c];
            acc = fmaf(ww.x, ffv[4*c+0], acc);
            acc = fmaf(ww.y, ffv[4*c+1], acc);
            acc = fmaf(ww.z, ffv[4*c+2], acc);
            acc = fmaf(ww.w, ffv[4*c+3], acc);
        }
        ov[d] = yv[d] + acc + b2[d];
    }
    __syncthreads();

    red[tid] = ov[tid] + ov[tid+256];
    __syncthreads();
    for (int s = 128; s > 0; s >>= 1) { if (tid < s) red[tid] += red[tid+s]; __syncthreads(); }
    if (tid == 0) s_m = red[0] * (1.0f/512.f);
    __syncthreads();
    {
        float t0 = ov[tid] - s_m, t1 = ov[tid+256] - s_m;
        red[tid] = t0*t0 + t1*t1;
        __syncthreads();
        for (int s = 128; s > 0; s >>= 1) { if (tid < s) red[tid] += red[tid+s]; __syncthreads(); }
        if (tid == 0) s_inv = 1.0f / sqrtf(red[0]*(1.0f/512.f) + 1e-5f);
        __syncthreads();
        float o0 = t0 * s_inv * ga2[tid]     + be2[tid];
        float o1 = t1 * s_inv * ga2[tid+256] + be2[tid+256];
        ov[tid] = o0; ov[tid+256] = o1;
        d_out[BB + (size_t)b*512 + tid]       = o0;
        d_out[BB + (size_t)b*512 + tid + 256] = o1;
    }
    __syncthreads();

    red[tid] = ov[tid]*Wout[tid] + ov[tid+256]*Wout[tid+256];
    __syncthreads();
    for (int s = 128; s > 0; s >>= 1) { if (tid < s) red[tid] += red[tid+s]; __syncthreads(); }
    if (tid == 0) d_out[b] = red[0] + bout[0];
}

// ================= host launcher =================
extern "C" void kernel_launch(void* const* d_in, const int* in_sizes, int n_in,
                              void* d_out, int out_size)
{
    const float* x    = (const float*)d_in[0];
    const float* Wq   = (const float*)d_in[1];
    const float* bq   = (const float*)d_in[2];
    const float* Wk   = (const float*)d_in[3];
    const float* bk   = (const float*)d_in[4];
    const float* Wv   = (const float*)d_in[5];
    const float* bv   = (const float*)d_in[6];
    const float* Wo   = (const float*)d_in[7];
    const float* bo   = (const float*)d_in[8];
    const float* W1   = (const float*)d_in[9];
    const float* b1   = (const float*)d_in[10];
    const float* W2   = (const float*)d_in[11];
    const float* b2   = (const float*)d_in[12];
    const float* ga1  = (const float*)d_in[13];
    const float* be1  = (const float*)d_in[14];
    const float* ga2  = (const float*)d_in[15];
    const float* be2  = (const float*)d_in[16];
    const float* Wout = (const float*)d_in[17];
    const float* bout = (const float*)d_in[18];
    float* out = (float*)d_out;

    const int rs_smem = (2*64*128 + 64) * (int)sizeof(float);
    cudaFuncSetAttribute(maxpass2_kernel,
                         cudaFuncAttributeMaxDynamicSharedMemorySize, M3_SMEM);
    cudaFuncSetAttribute(rescore2_kernel,
                         cudaFuncAttributeMaxDynamicSharedMemorySize, rs_smem);
    cudaFuncSetAttribute(topattn2_kernel,
                         cudaFuncAttributeMaxDynamicSharedMemorySize, TA_SMEM);

    cvt_kernel<<<CVT_XBLKS + 128, 256>>>(x, Wq);
    kv_kernel<<<dim3(128, 8, 2), 256>>>(x, Wk, bk, Wv, bv);
    qproj_kernel<<<dim3(256, 4), 256>>>(bq);
    stats_kernel<<<dim3(NBH, 4), 256>>>();
    statcomb_kernel<<<NBH, 64>>>();
    maxpass2_kernel<<<dim3(LL/128, NBH), 256, M3_SMEM>>>();
    topcand_kernel<<<NBH, 256>>>();
    qcand_kernel<<<dim3(2, NBH), 256>>>(x, Wq, bq);
    rescore2_kernel<<<dim3(NSPLIT, NBH), 256, rs_smem>>>();
    select40_kernel<<<NBH, 128>>>();
    topattn2_kernel<<<dim3(NS, NBH), 256, TA_SMEM>>>();
    final_kernel<<<BB, 256>>>(Wo, bo, W1, b1, W2, b2,
                              ga1, be1, ga2, be2, Wout, bout, out);
}

// round 17
// speedup vs baseline: 1.3036x; 1.1454x over previous
#include <cuda_runtime.h>
#include <cuda_bf16.h>
#include <math.h>
#include <stdint.h>

#define BB 8
#define LL 2048
#define DD 512
#define HH 8
#define DH 64
#define DFF 2048
#define UU 40
#define NCAND 128
#define NSPLIT 4
#define NS 4
#define NBH (BB*HH)

// ---------------- scratch (no allocs allowed) ----------------
__device__ float g_k[NBH*LL*DH];
__device__ float g_v[NBH*LL*DH];
__device__ __nv_bfloat16 g_xh[BB*LL*DD];    // bf16 input
__device__ __nv_bfloat16 g_wqt[DD*DD];      // Wq^T bf16  [n][e]
__device__ __nv_bfloat16 g_qh[NBH*LL*DH];   // bf16 q (approx)
__device__ __nv_bfloat16 g_kh[NBH*LL*DH];   // bf16 k
__device__ float g_M[NBH*LL];
__device__ float g_ksp[4*NBH*DH];           // stats partials
__device__ float g_vsp[4*NBH*DH];
__device__ float g_ksum[NBH*DH];
__device__ float g_vmean[NBH*DH];
__device__ int   g_cand[NBH*NCAND];
__device__ float g_qc[NBH*NCAND*DH];        // exact fp32 q for candidates
__device__ float g_rmaxp[NSPLIT*NBH*NCAND];
__device__ float g_dotc[NBH*NCAND];
__device__ int   g_topslot[NBH*UU];
__device__ float g_pm[NS*NBH*UU];
__device__ float g_pl[NS*NBH*UU];
__device__ float g_pO[NS*NBH*UU*DH];

__device__ __forceinline__ uint32_t smem_u32(const void* p) {
    uint32_t a;
    asm("{ .reg .u64 t; cvta.to.shared.u64 t, %1; cvt.u32.u64 %0, t; }"
        : "=r"(a) : "l"(p));
    return a;
}
#define SWZ(b) ((b) ^ (((b) >> 3) & 0x70))

__device__ __forceinline__ uint32_t f2ord(float f) {
    uint32_t u = __float_as_uint(f);
    return (u & 0x80000000u) ? ~u : (u | 0x80000000u);
}

// packed fp32x2 helpers (FFMA2)
#define FMA_X2(acc, a, b) \
    asm("fma.rn.f32x2 %0, %1, %2, %0;" : "+l"(acc) : "l"(a), "l"(b))
#define PACK_DUP(out, v) \
    asm("mov.b64 %0, {%1, %1};" : "=l"(out) : "r"(__float_as_uint(v)))
#define UNPACK_X2(lo, hi, v) \
    asm("mov.b64 {%0, %1}, %2;" : "=f"(lo), "=f"(hi) : "l"(v))

// ============ Kernel 0: x -> bf16, Wq -> bf16 transposed ============
#define CVT_XBLKS 4096
__global__ __launch_bounds__(256) void cvt_kernel(
    const float* __restrict__ x, const float* __restrict__ Wq)
{
    const int bidx = blockIdx.x, tid = threadIdx.x;
    if (bidx < CVT_XBLKS) {
        size_t base = (size_t)bidx*2048 + tid*8;
        float4 a = *(const float4*)&x[base];
        float4 b = *(const float4*)&x[base+4];
        *(__nv_bfloat162*)&g_xh[base]   = __nv_bfloat162(__float2bfloat16_rn(a.x), __float2bfloat16_rn(a.y));
        *(__nv_bfloat162*)&g_xh[base+2] = __nv_bfloat162(__float2bfloat16_rn(a.z), __float2bfloat16_rn(a.w));
        *(__nv_bfloat162*)&g_xh[base+4] = __nv_bfloat162(__float2bfloat16_rn(b.x), __float2bfloat16_rn(b.y));
        *(__nv_bfloat162*)&g_xh[base+6] = __nv_bfloat162(__float2bfloat16_rn(b.z), __float2bfloat16_rn(b.w));
    } else {
        int i = bidx - CVT_XBLKS;            // 0..127
        int n = i*4 + (tid >> 6);
        int e0 = tid & 63;
        #pragma unroll
        for (int j = 0; j < 8; j++) {
            int e = e0 + 64*j;
            g_wqt[n*512 + e] = __float2bfloat16_rn(Wq[(size_t)e*512 + n]);
        }
    }
}

// ======= Kernel 1: K/V projection (fp32, FFMA2 packed inner loop) ==========
__global__ __launch_bounds__(256) void kv_kernel(
    const float* __restrict__ x,
    const float* __restrict__ Wk, const float* __restrict__ bk,
    const float* __restrict__ Wv, const float* __restrict__ bv)
{
    const int z = blockIdx.z;
    const float* __restrict__ W    = (z==0) ? Wk : Wv;
    const float* __restrict__ bias = (z==0) ? bk : bv;
    float* __restrict__ outp       = (z==0) ? g_k : g_v;

    __shared__ float Xs[16][132];
    __shared__ float Ws[16][68];

    const int m0 = blockIdx.x * 128;
    const int n0 = blockIdx.y * 64;
    const int tid = threadIdx.x;
    const int tn = tid & 15;
    const int tm = tid >> 4;

    unsigned long long acc2[4][4];
    #pragma unroll
    for (int i2 = 0; i2 < 4; i2++)
        #pragma unroll
        for (int j = 0; j < 4; j++) acc2[i2][j] = 0ull;

    for (int k0 = 0; k0 < 512; k0 += 16) {
        #pragma unroll
        for (int it = 0; it < 2; it++) {
            int idx = tid + it*256;
            int r = idx >> 2, c = idx & 3;
            float4 xv = *(const float4*)&x[(size_t)(m0 + r)*512 + k0 + c*4];
            Xs[c*4+0][r] = xv.x; Xs[c*4+1][r] = xv.y;
            Xs[c*4+2][r] = xv.z; Xs[c*4+3][r] = xv.w;
        }
        {
            int r = tid >> 4, c = tid & 15;
            float4 wv = *(const float4*)&W[(size_t)(k0 + r)*512 + n0 + c*4];
            *(float4*)&Ws[r][c*4] = wv;
        }
        __syncthreads();
        #pragma unroll
        for (int kk = 0; kk < 16; kk++) {
            const unsigned long long* ap =
                (const unsigned long long*)&Xs[kk][tm*8];
            unsigned long long a2_0 = ap[0], a2_1 = ap[1];
            unsigned long long a2_2 = ap[2], a2_3 = ap[3];
            float4 b0 = *(float4*)&Ws[kk][tn*4];
            unsigned long long bd[4];
            PACK_DUP(bd[0], b0.x); PACK_DUP(bd[1], b0.y);
            PACK_DUP(bd[2], b0.z); PACK_DUP(bd[3], b0.w);
            #pragma unroll
            for (int j = 0; j < 4; j++) {
                FMA_X2(acc2[0][j], a2_0, bd[j]);
                FMA_X2(acc2[1][j], a2_1, bd[j]);
                FMA_X2(acc2[2][j], a2_2, bd[j]);
                FMA_X2(acc2[3][j], a2_3, bd[j]);
            }
        }
        __syncthreads();
    }

    float acc[8][4];
    #pragma unroll
    for (int i2 = 0; i2 < 4; i2++)
        #pragma unroll
        for (int j = 0; j < 4; j++) {
            float lo, hi;
            UNPACK_X2(lo, hi, acc2[i2][j]);
            acc[2*i2][j]   = lo;
            acc[2*i2+1][j] = hi;
        }

    const int h = n0 >> 6;
    float4 b4 = *(const float4*)&bias[n0 + tn*4];
    #pragma unroll
    for (int i = 0; i < 8; i++) {
        int r  = m0 + tm*8 + i;
        int bb = r >> 11, l = r & 2047;
        size_t base = ((size_t)(bb*HH + h)*LL + l)*64 + tn*4;
        float o[4] = {acc[i][0]+b4.x, acc[i][1]+b4.y, acc[i][2]+b4.z, acc[i][3]+b4.w};
        *(float4*)&outp[base] = make_float4(o[0],o[1],o[2],o[3]);
        if (z == 0) {
            *(__nv_bfloat162*)&g_kh[base]   =
                __nv_bfloat162(__float2bfloat16_rn(o[0]), __float2bfloat16_rn(o[1]));
            *(__nv_bfloat162*)&g_kh[base+2] =
                __nv_bfloat162(__float2bfloat16_rn(o[2]), __float2bfloat16_rn(o[3]));
        }
    }
}

// ---------------- mma helpers ----------------
__device__ __forceinline__ void ldmA(uint32_t* a, uint32_t addr) {
    asm volatile("ldmatrix.sync.aligned.m8n8.x4.shared.b16 {%0,%1,%2,%3}, [%4];"
        : "=r"(a[0]),"=r"(a[1]),"=r"(a[2]),"=r"(a[3]) : "r"(addr));
}
__device__ __forceinline__ void ldmB4(uint32_t* b, uint32_t addr) {
    asm volatile("ldmatrix.sync.aligned.m8n8.x4.shared.b16 {%0,%1,%2,%3}, [%4];"
        : "=r"(b[0]),"=r"(b[1]),"=r"(b[2]),"=r"(b[3]) : "r"(addr));
}
__device__ __forceinline__ void mma16816(float* c, const uint32_t* a, const uint32_t* b) {
    asm volatile(
        "mma.sync.aligned.m16n8k16.row.col.f32.bf16.bf16.f32 "
        "{%0,%1,%2,%3}, {%4,%5,%6,%7}, {%8,%9}, {%0,%1,%2,%3};"
        : "+f"(c[0]),"+f"(c[1]),"+f"(c[2]),"+f"(c[3])
        : "r"(a[0]),"r"(a[1]),"r"(a[2]),"r"(a[3]), "r"(b[0]),"r"(b[1]));
}

// ===== Kernel 2: Q projection in bf16 HMMA =====
#define QP_A 0
#define QP_B 8192
__global__ __launch_bounds__(256) void qproj_kernel(const float* __restrict__ bq)
{
    __shared__ char smem[24576];
    const uint32_t sb = smem_u32(smem);
    const int tid = threadIdx.x, wid = tid >> 5, lane = tid & 31;
    const int m0 = blockIdx.x * 64, n0 = blockIdx.y * 128;

    const int qg = wid >> 1, kg = wid & 1;
    const int ag = lane >> 3, ar = lane & 7;
    const int arow  = qg*16 + ((ag & 1) << 3) + ar;
    const int ahalf = (ag >> 1) << 3;
    const int bm = lane >> 3, brw = lane & 7;
    const int b_nboff = bm >> 1, b_half = (bm & 1) << 3;

    float acc[8][4];
    #pragma unroll
    for (int nb = 0; nb < 8; nb++)
        #pragma unroll
        for (int j = 0; j < 4; j++) acc[nb][j] = 0.f;

    for (int kc0 = 0; kc0 < 8; kc0++) {
        __syncthreads();
        #pragma unroll
        for (int it = 0; it < 2; it++) {
            int i = tid + it*256;
            int row = i >> 3, c = i & 7;
            const char* ap = (const char*)(g_xh + (size_t)(m0+row)*512 + kc0*64);
            *(uint4*)(smem + QP_A + SWZ(row*128 + c*16)) = *(const uint4*)(ap + c*16);
        }
        #pragma unroll
        for (int it = 0; it < 4; it++) {
            int i = tid + it*256;
            int row = i >> 3, c = i & 7;
            const char* bp = (const char*)(g_wqt + (size_t)(n0+row)*512 + kc0*64);
            *(uint4*)(smem + QP_B + SWZ(row*128 + c*16)) = *(const uint4*)(bp + c*16);
        }
        __syncthreads();

        #pragma unroll
        for (int kc = 0; kc < 4; kc++) {
            uint32_t Ah[4];
            ldmA(Ah, sb + QP_A + SWZ(arow*128 + (kc*16 + ahalf)*2));
            #pragma unroll
            for (int nbp = 0; nbp < 8; nbp += 2) {
                uint32_t Bh[4];
                int nrow = kg*64 + (nbp + b_nboff)*8 + brw;
                ldmB4(Bh, sb + QP_B + SWZ(nrow*128 + (kc*16 + b_half)*2));
                mma16816(acc[nbp],   Ah, Bh);
                mma16816(acc[nbp+1], Ah, Bh+2);
            }
        }
    }

    const int r_lo = m0 + qg*16 + (lane >> 2);
    const int colb = (lane & 3) * 2;
    #pragma unroll
    for (int nb = 0; nb < 8; nb++) {
        int n = n0 + kg*64 + nb*8 + colb;
        int h = n >> 6, d = n & 63;
        float2 bq2 = *(const float2*)&bq[n];
        #pragma unroll
        for (int rr = 0; rr < 2; rr++) {
            int m = r_lo + rr*8;
            int bb = m >> 11, l = m & 2047;
            float v0 = acc[nb][rr*2+0] + bq2.x;
            float v1 = acc[nb][rr*2+1] + bq2.y;
            *(__nv_bfloat162*)&g_qh[((size_t)(bb*HH + h)*LL + l)*64 + d] =
                __nv_bfloat162(__float2bfloat16_rn(v0), __float2bfloat16_rn(v1));
        }
    }
}

// ========== Kernel 3: key-sum & value-mean (4-way split + combine) =========
__global__ __launch_bounds__(256) void stats_kernel()
{
    const int bh = blockIdx.x, p4 = blockIdx.y;
    const int tid = threadIdx.x;
    const int d4 = tid & 15, r = tid >> 4;

    const float4* kp = (const float4*)(g_k + ((size_t)bh*LL + p4*512 + r*32)*64);
    const float4* vp = (const float4*)(g_v + ((size_t)bh*LL + p4*512 + r*32)*64);
    float4 ks = make_float4(0,0,0,0), vs = make_float4(0,0,0,0);
    #pragma unroll 4
    for (int s = 0; s < 32; s++) {
        float4 a = kp[s*16 + d4];
        float4 b = vp[s*16 + d4];
        ks.x += a.x; ks.y += a.y; ks.z += a.z; ks.w += a.w;
        vs.x += b.x; vs.y += b.y; vs.z += b.z; vs.w += b.w;
    }
    __shared__ float4 sk[256], sv[256];
    sk[tid] = ks; sv[tid] = vs;
    __syncthreads();
    for (int s = 8; s > 0; s >>= 1) {
        if (r < s) {
            float4 a = sk[tid + s*16], b = sv[tid + s*16];
            ks.x += a.x; ks.y += a.y; ks.z += a.z; ks.w += a.w;
            vs.x += b.x; vs.y += b.y; vs.z += b.z; vs.w += b.w;
            sk[tid] = ks; sv[tid] = vs;
        }
        __syncthreads();
    }
    if (r == 0) {
        *(float4*)&g_ksp[((size_t)p4*NBH + bh)*64 + d4*4] = ks;
        *(float4*)&g_vsp[((size_t)p4*NBH + bh)*64 + d4*4] = vs;
    }
}

__global__ __launch_bounds__(64) void statcomb_kernel()
{
    const int bh = blockIdx.x, d = threadIdx.x;
    float ks = 0.f, vs = 0.f;
    #pragma unroll
    for (int p = 0; p < 4; p++) {
        ks += g_ksp[((size_t)p*NBH + bh)*64 + d];
        vs += g_vsp[((size_t)p*NBH + bh)*64 + d];
    }
    g_ksum[bh*64 + d]  = ks;
    g_vmean[bh*64 + d] = vs * (1.0f/LL);
}

// ==== Kernel 4: approx QK^T row-max, 32-row warps ====
#define M3_QH 0
#define M3_KH 16384
#define M3_KS 32768
#define M3_MB 33024
#define M3_SMEM (M3_MB + 2*128*4)

__global__ __launch_bounds__(256,2) void maxpass2_kernel()
{
    extern __shared__ char smem[];
    const uint32_t sb = smem_u32(smem);
    const int tid = threadIdx.x, wid = tid >> 5, lane = tid & 31;
    const int bh = blockIdx.y, q0 = blockIdx.x * 128;

    if (tid < 64) *(float*)(smem + M3_KS + tid*4) = g_ksum[bh*64 + tid];

    {   // Q tile: 128 rows x 128B, SW128
        const char* qh = (const char*)(g_qh + ((size_t)bh*LL + q0)*64);
        #pragma unroll
        for (int it = 0; it < 4; it++) {
            int byte = (tid + it*256) * 16;
            *(uint4*)(smem + M3_QH + SWZ(byte)) = *(const uint4*)(qh + byte);
        }
    }

    const int qg = wid >> 1, kg = wid & 1;
    const int ag = lane >> 3, ar = lane & 7;
    const int arow0 = qg*32 + ((ag & 1) << 3) + ar;
    const int ahalf = (ag >> 1) << 3;
    const int bm = lane >> 3, brw = lane & 7;
    const int b_nboff = bm >> 1, b_half = (bm & 1) << 3;

    float rmax[2][2];
    rmax[0][0] = rmax[0][1] = rmax[1][0] = rmax[1][1] = -INFINITY;

    for (int kt = 0; kt < LL/128; kt++) {
        __syncthreads();
        {
            const char* kh = (const char*)(g_kh + ((size_t)bh*LL + kt*128)*64);
            #pragma unroll
            for (int it = 0; it < 4; it++) {
                int byte = (tid + it*256) * 16;
                *(uint4*)(smem + M3_KH + SWZ(byte)) = *(const uint4*)(kh + byte);
            }
        }
        __syncthreads();

        float acc[2][8][4];
        #pragma unroll
        for (int mt = 0; mt < 2; mt++)
            #pragma unroll
            for (int nb = 0; nb < 8; nb++)
                #pragma unroll
                for (int j = 0; j < 4; j++) acc[mt][nb][j] = 0.f;

        #pragma unroll
        for (int kc = 0; kc < 4; kc++) {
            uint32_t Ah0[4], Ah1[4];
            ldmA(Ah0, sb + M3_QH + SWZ(arow0*128        + (kc*16 + ahalf)*2));
            ldmA(Ah1, sb + M3_QH + SWZ((arow0+16)*128   + (kc*16 + ahalf)*2));
            #pragma unroll
            for (int nbp = 0; nbp < 8; nbp += 2) {
                uint32_t Bh[4];
                int key = kg*64 + (nbp + b_nboff)*8 + brw;
                ldmB4(Bh, sb + M3_KH + SWZ(key*128 + (kc*16 + b_half)*2));
                mma16816(acc[0][nbp],   Ah0, Bh);
                mma16816(acc[0][nbp+1], Ah0, Bh+2);
                mma16816(acc[1][nbp],   Ah1, Bh);
                mma16816(acc[1][nbp+1], Ah1, Bh+2);
            }
        }
        #pragma unroll
        for (int mt = 0; mt < 2; mt++)
            #pragma unroll
            for (int nb = 0; nb < 8; nb++) {
                rmax[mt][0] = fmaxf(rmax[mt][0], fmaxf(acc[mt][nb][0], acc[mt][nb][1]));
                rmax[mt][1] = fmaxf(rmax[mt][1], fmaxf(acc[mt][nb][2], acc[mt][nb][3]));
            }
    }

    #pragma unroll
    for (int mt = 0; mt < 2; mt++)
        #pragma unroll
        for (int hh = 0; hh < 2; hh++) {
            rmax[mt][hh] = fmaxf(rmax[mt][hh], __shfl_xor_sync(0xffffffffu, rmax[mt][hh], 1));
            rmax[mt][hh] = fmaxf(rmax[mt][hh], __shfl_xor_sync(0xffffffffu, rmax[mt][hh], 2));
        }
    float* mb = (float*)(smem + M3_MB);
    if ((lane & 3) == 0) {
        #pragma unroll
        for (int mt = 0; mt < 2; mt++) {
            int row = qg*32 + mt*16 + (lane >> 2);
            mb[kg*128 + row]     = rmax[mt][0];
            mb[kg*128 + row + 8] = rmax[mt][1];
        }
    }
    __syncthreads();
    if (tid < 128) {
        float m = fmaxf(mb[tid], mb[128 + tid]);
        float dot = 0.f;
        #pragma unroll
        for (int d = 0; d < 64; d++) {
            float qv = __bfloat162float(*(__nv_bfloat16*)(smem + M3_QH + SWZ(tid*128 + d*2)));
            dot = fmaf(qv, *(float*)(smem + M3_KS + d*4), dot);
        }
        g_M[(size_t)bh*LL + q0 + tid] = m - dot * (1.0f/LL);
    }
}

// ========== Kernel 5: top-128 candidates (bitonic, 512 threads) ============
__global__ __launch_bounds__(512) void topcand_kernel()
{
    const int bh = blockIdx.x, tid = threadIdx.x;
    __shared__ unsigned long long arr[LL];
    for (int i = tid; i < LL; i += 512) {
        uint32_t key = f2ord(g_M[(size_t)bh*LL + i]);
        arr[i] = ((unsigned long long)key << 32) | (uint32_t)i;
    }
    __syncthreads();
    for (int k = 2; k <= LL; k <<= 1) {
        for (int j = k >> 1; j > 0; j >>= 1) {
            for (int i = tid; i < LL; i += 512) {
                int l = i ^ j;
                if (l > i) {
                    unsigned long long a = arr[i], b = arr[l];
                    bool up = ((i & k) == 0);
                    if (up ? (a < b) : (a > b)) { arr[i] = b; arr[l] = a; }
                }
            }
            __syncthreads();
        }
    }
    if (tid < NCAND)
        g_cand[bh*NCAND + tid] = (int)(arr[tid] & 0xFFFFFFFFu);
}

// ===== Kernel 6: exact fp32 Q for candidates =====
__global__ __launch_bounds__(256) void qcand_kernel(
    const float* __restrict__ x, const float* __restrict__ Wq,
    const float* __restrict__ bq)
{
    const int bh = blockIdx.y, half = blockIdx.x;
    const int b = bh >> 3, h = bh & 7;
    const int tid = threadIdx.x;
    const int d4 = tid & 15, ec = tid >> 4;
    __shared__ float xr[512];
    __shared__ float4 p4[256];

    for (int c = 0; c < 64; c++) {
        int cand = half*64 + c;
        int l = g_cand[bh*NCAND + cand];
        __syncthreads();
        *(float2*)&xr[tid*2] = *(const float2*)&x[((size_t)b*LL + l)*512 + tid*2];
        __syncthreads();

        float4 acc = make_float4(0.f,0.f,0.f,0.f);
        #pragma unroll 8
        for (int e = ec*32; e < ec*32 + 32; e++) {
            float xv = xr[e];
            float4 w = *(const float4*)&Wq[(size_t)e*512 + h*64 + d4*4];
            acc.x = fmaf(xv, w.x, acc.x); acc.y = fmaf(xv, w.y, acc.y);
            acc.z = fmaf(xv, w.z, acc.z); acc.w = fmaf(xv, w.w, acc.w);
        }
        p4[tid] = acc;
        __syncthreads();
        for (int s = 8; s > 0; s >>= 1) {
            if (ec < s) {
                float4 o = p4[tid + s*16];
                acc.x += o.x; acc.y += o.y; acc.z += o.z; acc.w += o.w;
                p4[tid] = acc;
            }
            __syncthreads();
        }
        if (ec == 0) {
            float4 bqv = *(const float4*)&bq[h*64 + d4*4];
            *(float4*)&g_qc[((size_t)bh*NCAND + cand)*64 + d4*4] =
                make_float4(acc.x+bqv.x, acc.y+bqv.y, acc.z+bqv.z, acc.w+bqv.w);
        }
    }
}

// ========== Kernel 7: exact fp32 rescore — tiled GEMM over key splits =======
__global__ __launch_bounds__(256,2) void rescore2_kernel()
{
    extern __shared__ float dsm[];
    float* Qs = dsm;
    float* Ks = dsm + 64*128;
    float* ks = dsm + 2*64*128;

    const int bh = blockIdx.y;
    const int sp = blockIdx.x;
    const int tid = threadIdx.x;
    const int tx  = tid & 15;
    const int ty  = tid >> 4;

    if (tid < 64) ks[tid] = g_ksum[bh*64 + tid];

    #pragma unroll
    for (int it = 0; it < 8; it++) {
        int idx = tid + it*256;
        int cc = idx & 127, d4 = idx >> 7;
        float4 v = *(const float4*)&g_qc[((size_t)bh*NCAND + cc)*64 + d4*4];
        Qs[(4*d4+0)*128 + cc] = v.x; Qs[(4*d4+1)*128 + cc] = v.y;
        Qs[(4*d4+2)*128 + cc] = v.z; Qs[(4*d4+3)*128 + cc] = v.w;
    }

    float rmax[8];
    #pragma unroll
    for (int i = 0; i < 8; i++) rmax[i] = -INFINITY;

    const int kt0 = sp * (LL/128/NSPLIT);
    for (int kt = kt0; kt < kt0 + LL/128/NSPLIT; kt++) {
        __syncthreads();
        #pragma unroll
        for (int it = 0; it < 8; it++) {
            int idx = tid + it*256;
            int ss = idx & 127, d4 = idx >> 7;
            float4 v = *(const float4*)&g_k[((size_t)bh*LL + kt*128 + ss)*64 + d4*4];
            Ks[(4*d4+0)*128 + ss] = v.x; Ks[(4*d4+1)*128 + ss] = v.y;
            Ks[(4*d4+2)*128 + ss] = v.z; Ks[(4*d4+3)*128 + ss] = v.w;
        }
        __syncthreads();

        float acc[8][8];
        #pragma unroll
        for (int i = 0; i < 8; i++)
            #pragma unroll
            for (int j = 0; j < 8; j++) acc[i][j] = 0.f;

        #pragma unroll 4
        for (int kk = 0; kk < 64; kk++) {
            float4 qa = *(float4*)&Qs[kk*128 + ty*8];
            float4 qb = *(float4*)&Qs[kk*128 + ty*8 + 4];
            float4 ka = *(float4*)&Ks[kk*128 + tx*8];
            float4 kb = *(float4*)&Ks[kk*128 + tx*8 + 4];
            float am[8] = {qa.x,qa.y,qa.z,qa.w,qb.x,qb.y,qb.z,qb.w};
            float bm[8] = {ka.x,ka.y,ka.z,ka.w,kb.x,kb.y,kb.z,kb.w};
            #pragma unroll
            for (int i = 0; i < 8; i++)
                #pragma unroll
                for (int j = 0; j < 8; j++)
                    acc[i][j] = fmaf(am[i], bm[j], acc[i][j]);
        }
        #pragma unroll
        for (int i = 0; i < 8; i++) {
            float m = acc[i][0];
            #pragma unroll
            for (int j = 1; j < 8; j++) m = fmaxf(m, acc[i][j]);
            rmax[i] = fmaxf(rmax[i], m);
        }
    }

    float dotv[8];
    #pragma unroll
    for (int i = 0; i < 8; i++) dotv[i] = 0.f;
    if (sp == 0) {
        #pragma unroll
        for (int c = 0; c < 4; c++) {
            float kv = ks[tx*4 + c];
            #pragma unroll
            for (int i = 0; i < 8; i++)
                dotv[i] = fmaf(Qs[(tx*4+c)*128 + ty*8 + i], kv, dotv[i]);
        }
    }
    #pragma unroll
    for (int i = 0; i < 8; i++) {
        float m = rmax[i], dsum = dotv[i];
        #pragma unroll
        for (int off = 8; off > 0; off >>= 1) {
            m    = fmaxf(m, __shfl_xor_sync(0xffffffffu, m, off, 16));
            dsum +=          __shfl_xor_sync(0xffffffffu, dsum, off, 16);
        }
        if (tx == 0) {
            int cc = ty*8 + i;
            g_rmaxp[((size_t)sp*NBH + bh)*NCAND + cc] = m;
            if (sp == 0) g_dotc[bh*NCAND + cc] = dsum;
        }
    }
}

// ========== Kernel 8: combine splits + exact top-40 (slots) ================
__global__ __launch_bounds__(128) void select40_kernel()
{
    const int bh = blockIdx.x, tid = threadIdx.x;
    __shared__ unsigned long long arr[NCAND];
    {
        float m = -INFINITY;
        #pragma unroll
        for (int sp = 0; sp < NSPLIT; sp++)
            m = fmaxf(m, g_rmaxp[((size_t)sp*NBH + bh)*NCAND + tid]);
        float Mex = m - g_dotc[bh*NCAND + tid] * (1.0f/LL);
        arr[tid] = ((unsigned long long)f2ord(Mex) << 32) | (uint32_t)tid;
    }
    __syncthreads();
    for (int k = 2; k <= NCAND; k <<= 1) {
        for (int j = k >> 1; j > 0; j >>= 1) {
            int l = tid ^ j;
            if (l > tid) {
                unsigned long long a = arr[tid], b = arr[l];
                bool up = ((tid & k) == 0);
                if (up ? (a < b) : (a > b)) { arr[tid] = b; arr[l] = a; }
            }
            __syncthreads();
        }
    }
    if (tid < UU)
        g_topslot[bh*UU + tid] = (int)(arr[tid] & 0xFFFFFFFFu);
}

// ===== Kernel 9: flash-style attention, all 40 queries per (bh,split) =======
#define TA_QS 0
#define TA_KT 10240
#define TA_VT (TA_KT + 32768)
#define TA_SC (TA_VT + 32768)
#define TA_IDX (TA_SC + 20480)
#define TA_SMEM (TA_IDX + 256)

__global__ __launch_bounds__(256) void topattn2_kernel()
{
    extern __shared__ char smem[];
    float* qs = (float*)(smem + TA_QS);
    float* Kt = (float*)(smem + TA_KT);
    float* Vt = (float*)(smem + TA_VT);
    float* sc = (float*)(smem + TA_SC);
    int*   idx = (int*)(smem + TA_IDX);

    const int sp = blockIdx.x, bh = blockIdx.y;
    const int tid = threadIdx.x, w = tid >> 5, lane = tid & 31;

    if (tid < UU) idx[tid] = g_topslot[bh*UU + tid];
    __syncthreads();
    for (int i = tid; i < UU*16; i += 256) {
        int r = i >> 4, c = i & 15;
        float4 v = *(const float4*)&g_qc[((size_t)bh*NCAND + idx[r])*64 + c*4];
        qs[r*64 + c*4+0] = v.x*0.125f; qs[r*64 + c*4+1] = v.y*0.125f;
        qs[r*64 + c*4+2] = v.z*0.125f; qs[r*64 + c*4+3] = v.w*0.125f;
    }

    float m[5], l[5], O[5][2];
    #pragma unroll
    for (int qi = 0; qi < 5; qi++) {
        m[qi] = -INFINITY; l[qi] = 0.f; O[qi][0] = 0.f; O[qi][1] = 0.f;
    }

    const int kt0 = sp * (LL/128/NS);
    for (int kt = kt0; kt < kt0 + LL/128/NS; kt++) {
        __syncthreads();
        #pragma unroll
        for (int it = 0; it < 8; it++) {
            int i = tid + it*256;
            int ss = i & 127, d4 = i >> 7;
            float4 v = *(const float4*)&g_k[((size_t)bh*LL + kt*128 + ss)*64 + d4*4];
            Kt[(4*d4+0)*128 + ss] = v.x; Kt[(4*d4+1)*128 + ss] = v.y;
            Kt[(4*d4+2)*128 + ss] = v.z; Kt[(4*d4+3)*128 + ss] = v.w;
        }
        #pragma unroll
        for (int it = 0; it < 8; it++) {
            int i = tid + it*256;
            int ss = i >> 4, c = i & 15;
            *(float4*)&Vt[ss*64 + c*4] =
                *(const float4*)&g_v[((size_t)bh*LL + kt*128 + ss)*64 + c*4];
        }
        __syncthreads();

        float s4[5][4];
        #pragma unroll
        for (int qi = 0; qi < 5; qi++)
            #pragma unroll
            for (int j = 0; j < 4; j++) s4[qi][j] = 0.f;

        #pragma unroll 4
        for (int d = 0; d < 64; d++) {
            float4 kv = *(float4*)&Kt[d*128 + lane*4];
            #pragma unroll
            for (int qi = 0; qi < 5; qi++) {
                float qv = qs[(w*5 + qi)*64 + d];
                s4[qi][0] = fmaf(qv, kv.x, s4[qi][0]);
                s4[qi][1] = fmaf(qv, kv.y, s4[qi][1]);
                s4[qi][2] = fmaf(qv, kv.z, s4[qi][2]);
                s4[qi][3] = fmaf(qv, kv.w, s4[qi][3]);
            }
        }

        float scale[5];
        #pragma unroll
        for (int qi = 0; qi < 5; qi++) {
            float tm = fmaxf(fmaxf(s4[qi][0], s4[qi][1]), fmaxf(s4[qi][2], s4[qi][3]));
            #pragma unroll
            for (int off = 16; off > 0; off >>= 1)
                tm = fmaxf(tm, __shfl_xor_sync(0xffffffffu, tm, off));
            float mn = fmaxf(m[qi], tm);
            scale[qi] = expf(m[qi] - mn);
            float4 p;
            p.x = expf(s4[qi][0] - mn); p.y = expf(s4[qi][1] - mn);
            p.z = expf(s4[qi][2] - mn); p.w = expf(s4[qi][3] - mn);
            *(float4*)&sc[(w*5 + qi)*128 + lane*4] = p;
            float ls = p.x + p.y + p.z + p.w;
            #pragma unroll
            for (int off = 16; off > 0; off >>= 1)
                ls += __shfl_xor_sync(0xffffffffu, ls, off);
            l[qi] = l[qi]*scale[qi] + ls;
            m[qi] = mn;
        }
        __syncwarp();

        #pragma unroll
        for (int qi = 0; qi < 5; qi++) { O[qi][0] *= scale[qi]; O[qi][1] *= scale[qi]; }

        #pragma unroll 4
        for (int s = 0; s < 128; s++) {
            float2 vv = *(float2*)&Vt[s*64 + lane*2];
            #pragma unroll
            for (int qi = 0; qi < 5; qi++) {
                float p = sc[(w*5 + qi)*128 + s];
                O[qi][0] = fmaf(p, vv.x, O[qi][0]);
                O[qi][1] = fmaf(p, vv.y, O[qi][1]);
            }
        }
        __syncwarp();
    }

    #pragma unroll
    for (int qi = 0; qi < 5; qi++) {
        int r = w*5 + qi;
        size_t base = ((size_t)(sp*NBH + bh)*UU + r);
        *(float2*)&g_pO[base*64 + lane*2] = make_float2(O[qi][0], O[qi][1]);
        if (lane == 0) { g_pm[base] = m[qi]; g_pl[base] = l[qi]; }
    }
}

// ================= Kernel 10: decoder tail (per-batch, 4-way merge) ========
__global__ __launch_bounds__(256) void final_kernel(
    const float* __restrict__ Wo, const float* __restrict__ bo,
    const float* __restrict__ W1, const float* __restrict__ b1,
    const float* __restrict__ W2, const float* __restrict__ b2,
    const float* __restrict__ ga1, const float* __restrict__ be1,
    const float* __restrict__ ga2, const float* __restrict__ be2,
    const float* __restrict__ Wout, const float* __restrict__ bout,
    float* __restrict__ d_out)
{
    const int b = blockIdx.x, tid = threadIdx.x;
    __shared__ float ctxm[512], av[512], yv[512], ffv[2048], ov[512], red[256];
    __shared__ float wS[NS][HH*UU];
    __shared__ float s_m, s_inv;

    for (int i = tid; i < HH*UU; i += 256) {
        int h = i / UU, r = i % UU;
        float mv[NS], lv[NS];
        float mm = -INFINITY;
        #pragma unroll
        for (int sp = 0; sp < NS; sp++) {
            size_t bb = (size_t)(sp*NBH + b*HH + h)*UU + r;
            mv[sp] = g_pm[bb]; lv[sp] = g_pl[bb];
            mm = fmaxf(mm, mv[sp]);
        }
        float den = 0.f, wv[NS];
        #pragma unroll
        for (int sp = 0; sp < NS; sp++) {
            wv[sp] = expf(mv[sp] - mm);
            den += wv[sp]*lv[sp];
        }
        #pragma unroll
        for (int sp = 0; sp < NS; sp++) wS[sp][i] = wv[sp]/den;
    }
    __syncthreads();

    #pragma unroll
    for (int k = 0; k < 2; k++) {
        int d = tid + k*256;
        int h = d >> 6, dd = d & 63;
        int bh = b*HH + h;
        float val = g_vmean[bh*64 + dd] * (float)(LL - UU);
        for (int r = 0; r < UU; r++) {
            #pragma unroll
            for (int sp = 0; sp < NS; sp++) {
                float o = g_pO[((size_t)(sp*NBH + bh)*UU + r)*64 + dd];
                val += wS[sp][h*UU + r]*o;
            }
        }
        ctxm[d] = val * (1.0f/LL);
    }
    __syncthreads();

    #pragma unroll
    for (int k = 0; k < 2; k++) {
        int d = tid + k*256;
        float acc = 0.f;
        for (int e = 0; e < 512; e++)
            acc = fmaf(ctxm[e], Wo[(size_t)e*512 + d], acc);
        av[d] = acc + bo[d];
    }
    __syncthreads();

    red[tid] = 2.f*av[tid] + 2.f*av[tid+256];
    __syncthreads();
    for (int s = 128; s > 0; s >>= 1) { if (tid < s) red[tid] += red[tid+s]; __syncthreads(); }
    if (tid == 0) s_m = red[0] * (1.0f/512.f);
    __syncthreads();
    {
        float t0 = 2.f*av[tid] - s_m, t1 = 2.f*av[tid+256] - s_m;
        red[tid] = t0*t0 + t1*t1;
        __syncthreads();
        for (int s = 128; s > 0; s >>= 1) { if (tid < s) red[tid] += red[tid+s]; __syncthreads(); }
        if (tid == 0) s_inv = 1.0f / sqrtf(red[0]*(1.0f/512.f) + 1e-5f);
        __syncthreads();
        yv[tid]     = t0 * s_inv * ga1[tid]     + be1[tid];
        yv[tid+256] = t1 * s_inv * ga1[tid+256] + be1[tid+256];
    }
    __syncthreads();

    #pragma unroll
    for (int it = 0; it < 8; it++) {
        int f = tid + it*256;
        const float4* wp = (const float4*)&W1[(size_t)f*512];
        float acc = 0.f;
        #pragma unroll 8
        for (int c = 0; c < 128; c++) {
            float4 ww = wp[c];
            acc = fmaf(ww.x, yv[4*c+0], acc);
            acc = fmaf(ww.y, yv[4*c+1], acc);
            acc = fmaf(ww.z, yv[4*c+2], acc);
            acc = fmaf(ww.w, yv[4*c+3], acc);
        }
        ffv[f] = fmaxf(acc + b1[f], 0.f);
    }
    __syncthreads();

    #pragma unroll
    for (int k = 0; k < 2; k++) {
        int d = tid + k*256;
        const float4* wp = (const float4*)&W2[(size_t)d*2048];
        float acc = 0.f;
        #pragma unroll 8
        for (int c = 0; c < 512; c++) {
            float4 ww = wp[c];
            acc = fmaf(ww.x, ffv[4*c+0], acc);
            acc = fmaf(ww.y, ffv[4*c+1], acc);
            acc = fmaf(ww.z, ffv[4*c+2], acc);
            acc = fmaf(ww.w, ffv[4*c+3], acc);
        }
        ov[d] = yv[d] + acc + b2[d];
    }
    __syncthreads();

    red[tid] = ov[tid] + ov[tid+256];
    __syncthreads();
    for (int s = 128; s > 0; s >>= 1) { if (tid < s) red[tid] += red[tid+s]; __syncthreads(); }
    if (tid == 0) s_m = red[0] * (1.0f/512.f);
    __syncthreads();
    {
        float t0 = ov[tid] - s_m, t1 = ov[tid+256] - s_m;
        red[tid] = t0*t0 + t1*t1;
        __syncthreads();
        for (int s = 128; s > 0; s >>= 1) { if (tid < s) red[tid] += red[tid+s]; __syncthreads(); }
        if (tid == 0) s_inv = 1.0f / sqrtf(red[0]*(1.0f/512.f) + 1e-5f);
        __syncthreads();
        float o0 = t0 * s_inv * ga2[tid]     + be2[tid];
        float o1 = t1 * s_inv * ga2[tid+256] + be2[tid+256];
        ov[tid] = o0; ov[tid+256] = o1;
        d_out[BB + (size_t)b*512 + tid]       = o0;
        d_out[BB + (size_t)b*512 + tid + 256] = o1;
    }
    __syncthreads();

    red[tid] = ov[tid]*Wout[tid] + ov[tid+256]*Wout[tid+256];
    __syncthreads();
    for (int s = 128; s > 0; s >>= 1) { if (tid < s) red[tid] += red[tid+s]; __syncthreads(); }
    if (tid == 0) d_out[b] = red[0] + bout[0];
}

// ================= host launcher =================
extern "C" void kernel_launch(void* const* d_in, const int* in_sizes, int n_in,
                              void* d_out, int out_size)
{
    const float* x    = (const float*)d_in[0];
    const float* Wq   = (const float*)d_in[1];
    const float* bq   = (const float*)d_in[2];
    const float* Wk   = (const float*)d_in[3];
    const float* bk   = (const float*)d_in[4];
    const float* Wv   = (const float*)d_in[5];
    const float* bv   = (const float*)d_in[6];
    const float* Wo   = (const float*)d_in[7];
    const float* bo   = (const float*)d_in[8];
    const float* W1   = (const float*)d_in[9];
    const float* b1   = (const float*)d_in[10];
    const float* W2   = (const float*)d_in[11];
    const float* b2   = (const float*)d_in[12];
    const float* ga1  = (const float*)d_in[13];
    const float* be1  = (const float*)d_in[14];
    const float* ga2  = (const float*)d_in[15];
    const float* be2  = (const float*)d_in[16];
    const float* Wout = (const float*)d_in[17];
    const float* bout = (const float*)d_in[18];
    float* out = (float*)d_out;

    const int rs_smem = (2*64*128 + 64) * (int)sizeof(float);
    cudaFuncSetAttribute(maxpass2_kernel,
                         cudaFuncAttributeMaxDynamicSharedMemorySize, M3_SMEM);
    cudaFuncSetAttribute(rescore2_kernel,
                         cudaFuncAttributeMaxDynamicSharedMemorySize, rs_smem);
    cudaFuncSetAttribute(topattn2_kernel,
                         cudaFuncAttributeMaxDynamicSharedMemorySize, TA_SMEM);

    cvt_kernel<<<CVT_XBLKS + 128, 256>>>(x, Wq);
    kv_kernel<<<dim3(128, 8, 2), 256>>>(x, Wk, bk, Wv, bv);
    qproj_kernel<<<dim3(256, 4), 256>>>(bq);
    stats_kernel<<<dim3(NBH, 4), 256>>>();
    statcomb_kernel<<<NBH, 64>>>();
    maxpass2_kernel<<<dim3(LL/128, NBH), 256, M3_SMEM>>>();
    topcand_kernel<<<NBH, 512>>>();
    qcand_kernel<<<dim3(2, NBH), 256>>>(x, Wq, bq);
    rescore2_kernel<<<dim3(NSPLIT, NBH), 256, rs_smem>>>();
    select40_kernel<<<NBH, 128>>>();
    topattn2_kernel<<<dim3(NS, NBH), 256, TA_SMEM>>>();
    final_kernel<<<BB, 256>>>(Wo, bo, W1, b1, W2, b2,
                              ga1, be1, ga2, be2, Wout, bout, out);
}